// round 2
// baseline (speedup 1.0000x reference)
#include <cuda_runtime.h>
#include <cuda_bf16.h>
#include <math.h>

#define DIMN   1024
#define SEQL   1024
#define BATCHN 4
#define NTOK   (BATCHN*SEQL)     /* 4096 */
#define NBLK   (BATCHN*128)      /* 512 tokens of vec */
#define QKV_LD 1536
#define EPSV   1e-6f

/* ---------------- scratch (device globals: no allocation allowed) -------- */
__device__ float g_silu_vec[NBLK*DIMN];
__device__ float g_mod_a[NBLK*3*DIMN];
__device__ float g_mod_f[NBLK*3*DIMN];
__device__ float g_xn[NTOK*DIMN];
__device__ float g_qkv[NTOK*QKV_LD];
__device__ float g_attn[NTOK*DIMN];
__device__ float g_h[NTOK*DIMN];
__device__ float g_hn[NTOK*DIMN];
__device__ float g_g1[NTOK*DIMN];
__device__ float g_g3[NTOK*DIMN];

/* ---------------- elementwise kernels ------------------------------------ */
__global__ __launch_bounds__(256) void silu_kernel(const float* __restrict__ in,
                                                   float* __restrict__ out) {
    int i = blockIdx.x * 256 + threadIdx.x;           // one float4 per thread
    float4 v = ((const float4*)in)[i];
    float4 o;
    o.x = v.x / (1.f + __expf(-v.x));
    o.y = v.y / (1.f + __expf(-v.y));
    o.z = v.z / (1.f + __expf(-v.z));
    o.w = v.w / (1.f + __expf(-v.w));
    ((float4*)out)[i] = o;
}

__global__ __launch_bounds__(256) void swiglu_kernel(float* __restrict__ g1,
                                                     const float* __restrict__ g3) {
    int i = blockIdx.x * 256 + threadIdx.x;
    float4 a = ((float4*)g1)[i];
    float4 b = ((const float4*)g3)[i];
    float4 o;
    o.x = (a.x / (1.f + __expf(-a.x))) * b.x;
    o.y = (a.y / (1.f + __expf(-a.y))) * b.y;
    o.z = (a.z / (1.f + __expf(-a.z))) * b.z;
    o.w = (a.w / (1.f + __expf(-a.w))) * b.w;
    ((float4*)g1)[i] = o;
}

/* rmsnorm + adaLN modulate: out = rms(x)*w*(1+scale) + shift                */
__global__ __launch_bounds__(256) void rmsnorm_mod_kernel(
    const float* __restrict__ X, const float* __restrict__ w,
    const float* __restrict__ mod, float* __restrict__ out) {
    int m = blockIdx.x;                 // token 0..4095
    int tid = threadIdx.x;
    float4 v = ((const float4*)(X + (size_t)m*DIMN))[tid];
    float ss = v.x*v.x + v.y*v.y + v.z*v.z + v.w*v.w;
    #pragma unroll
    for (int o = 16; o; o >>= 1) ss += __shfl_xor_sync(0xffffffffu, ss, o);
    __shared__ float red[8];
    if ((tid & 31) == 0) red[tid >> 5] = ss;
    __syncthreads();
    float tot = red[0]+red[1]+red[2]+red[3]+red[4]+red[5]+red[6]+red[7];
    float rms = rsqrtf(tot * (1.f/DIMN) + EPSV);
    const float* mrow = mod + (size_t)(m >> 3) * (3*DIMN);
    float4 sh = *(const float4*)(mrow + tid*4);
    float4 sc = *(const float4*)(mrow + DIMN + tid*4);
    float4 wv = ((const float4*)w)[tid];
    float4 o;
    o.x = v.x*rms*wv.x*(1.f+sc.x) + sh.x;
    o.y = v.y*rms*wv.y*(1.f+sc.y) + sh.y;
    o.z = v.z*rms*wv.z*(1.f+sc.z) + sh.z;
    o.w = v.w*rms*wv.w*(1.f+sc.w) + sh.w;
    ((float4*)(out + (size_t)m*DIMN))[tid] = o;
}

/* interleaved RoPE on q (16 heads) + k (4 heads) inside the qkv buffer      */
__global__ __launch_bounds__(256) void rope_kernel(float* __restrict__ qkv,
                                                   const float* __restrict__ cosb,
                                                   const float* __restrict__ sinb) {
    int id = blockIdx.x * 256 + threadIdx.x;   // 4096*20*32 = 2621440 threads
    int d  = id & 31;  id >>= 5;
    int hh = id % 20;  int tg = id / 20;       // tg = b*1024 + t
    int col = (hh < 16) ? hh*64 : 1024 + (hh-16)*64;
    float* p = qkv + (size_t)tg*QKV_LD + col + 2*d;
    int t = tg & (SEQL-1);
    float c = cosb[t*32 + d], s = sinb[t*32 + d];
    float x1 = p[0], x2 = p[1];
    p[0] = x1*c - x2*s;
    p[1] = x1*s + x2*c;
}

/* ---------------- SGEMM: C(M,N) = A(M,K) @ B(N,K)^T, fused epilogues ------ */
#define BM 128
#define BN 64
#define BK 16
#define APAD (BM+4)
#define BPAD (BN+4)

/* EPI 0: C = acc ; EPI 1: C = acc + bias[n]
   EPI 2: C = resid[m,n] + mod[(m>>3)*3072 + goff + n] * acc                  */
template<int EPI>
__global__ __launch_bounds__(256) void gemm_nt(
    const float* __restrict__ A, int lda,
    const float* __restrict__ B, int ldb,
    float* __restrict__ C, int ldc,
    int K,
    const float* __restrict__ bias,
    const float* __restrict__ resid, int ldr,
    const float* __restrict__ mod, int goff) {
    __shared__ float As[2][BK][APAD];
    __shared__ float Bs[2][BK][BPAD];
    int tid = threadIdx.x;
    int tm = tid >> 4, tn = tid & 15;
    int m0 = blockIdx.y * BM, n0 = blockIdx.x * BN;
    const float* Ag = A + (size_t)m0 * lda;
    const float* Bg = B + (size_t)n0 * ldb;

    /* preload tile 0 */
    {
        #pragma unroll
        for (int i = 0; i < 2; i++) {
            int idx = tid + i*256, r = idx >> 2, kq = (idx & 3)*4;
            float4 v = *(const float4*)(Ag + (size_t)r*lda + kq);
            As[0][kq+0][r]=v.x; As[0][kq+1][r]=v.y; As[0][kq+2][r]=v.z; As[0][kq+3][r]=v.w;
        }
        int r = tid >> 2, kq = (tid & 3)*4;
        float4 v = *(const float4*)(Bg + (size_t)r*ldb + kq);
        Bs[0][kq+0][r]=v.x; Bs[0][kq+1][r]=v.y; Bs[0][kq+2][r]=v.z; Bs[0][kq+3][r]=v.w;
    }
    __syncthreads();

    float acc[8][4];
    #pragma unroll
    for (int i=0;i<8;i++)
        #pragma unroll
        for (int j=0;j<4;j++) acc[i][j]=0.f;

    int nk = K / BK;
    float4 ra[2], rb;
    for (int kt = 0; kt < nk; kt++) {
        int cur = kt & 1;
        if (kt + 1 < nk) {
            int k0 = (kt+1)*BK;
            #pragma unroll
            for (int i = 0; i < 2; i++) {
                int idx = tid + i*256, r = idx >> 2, kq = (idx & 3)*4;
                ra[i] = *(const float4*)(Ag + (size_t)r*lda + k0 + kq);
            }
            int r = tid >> 2, kq = (tid & 3)*4;
            rb = *(const float4*)(Bg + (size_t)r*ldb + k0 + kq);
        }
        #pragma unroll
        for (int kk = 0; kk < BK; kk++) {
            float4 a0 = *(const float4*)&As[cur][kk][tm*8];
            float4 a1 = *(const float4*)&As[cur][kk][tm*8+4];
            float4 b0 = *(const float4*)&Bs[cur][kk][tn*4];
            float a[8] = {a0.x,a0.y,a0.z,a0.w,a1.x,a1.y,a1.z,a1.w};
            float bb[4] = {b0.x,b0.y,b0.z,b0.w};
            #pragma unroll
            for (int i=0;i<8;i++)
                #pragma unroll
                for (int j=0;j<4;j++)
                    acc[i][j] = fmaf(a[i], bb[j], acc[i][j]);
        }
        if (kt + 1 < nk) {
            int nxt = cur ^ 1;
            #pragma unroll
            for (int i = 0; i < 2; i++) {
                int idx = tid + i*256, r = idx >> 2, kq = (idx & 3)*4;
                As[nxt][kq+0][r]=ra[i].x; As[nxt][kq+1][r]=ra[i].y;
                As[nxt][kq+2][r]=ra[i].z; As[nxt][kq+3][r]=ra[i].w;
            }
            int r = tid >> 2, kq = (tid & 3)*4;
            Bs[nxt][kq+0][r]=rb.x; Bs[nxt][kq+1][r]=rb.y;
            Bs[nxt][kq+2][r]=rb.z; Bs[nxt][kq+3][r]=rb.w;
        }
        __syncthreads();
    }

    #pragma unroll
    for (int i = 0; i < 8; i++) {
        int m = m0 + tm*8 + i;
        int n = n0 + tn*4;
        float4 out;
        if (EPI == 0) {
            out.x=acc[i][0]; out.y=acc[i][1]; out.z=acc[i][2]; out.w=acc[i][3];
        } else if (EPI == 1) {
            float4 bv = *(const float4*)(bias + n);
            out.x=acc[i][0]+bv.x; out.y=acc[i][1]+bv.y;
            out.z=acc[i][2]+bv.z; out.w=acc[i][3]+bv.w;
        } else {
            float4 gv = *(const float4*)(mod + (size_t)(m>>3)*(3*DIMN) + goff + n);
            float4 rv = *(const float4*)(resid + (size_t)m*ldr + n);
            out.x = rv.x + gv.x*acc[i][0];
            out.y = rv.y + gv.y*acc[i][1];
            out.z = rv.z + gv.z*acc[i][2];
            out.w = rv.w + gv.w*acc[i][3];
        }
        *(float4*)(C + (size_t)m*ldc + n) = out;
    }
}

/* ---------------- block-causal flash attention ---------------------------- */
#define TPAD 68
#define ATT_SMEM (4*64*TPAD*4 + 2*64*4)

__global__ __launch_bounds__(256) void attn_kernel(const float* __restrict__ qkv,
                                                   float* __restrict__ outp) {
    extern __shared__ float sm[];
    float* Qs = sm;
    float* Ks = Qs + 64*TPAD;
    float* Vt = Ks + 64*TPAD;
    float* Ps = Vt + 64*TPAD;
    float* s_alpha = Ps + 64*TPAD;
    float* s_linv  = s_alpha + 64;

    int qt = blockIdx.x, h = blockIdx.y, b = blockIdx.z;
    int tid = threadIdx.x;
    int rg = tid >> 4, cg = tid & 15;

    const float* qbase = qkv + (size_t)b*SEQL*QKV_LD + h*64;
    const float* kbase = qkv + (size_t)b*SEQL*QKV_LD + 1024 + (h>>2)*64;
    const float* vbase = kbase + 256;

    {   int r = tid >> 2, q4 = tid & 3;
        #pragma unroll
        for (int ii = 0; ii < 4; ii++) {
            int c = (q4 + ii*4)*4;
            *(float4*)&Qs[r*TPAD + c] =
                *(const float4*)(qbase + (size_t)(qt*64 + r)*QKV_LD + c);
        }
    }
    float o[4][4];
    #pragma unroll
    for (int i=0;i<4;i++)
        #pragma unroll
        for (int j=0;j<4;j++) o[i][j]=0.f;
    float mrow = -1e30f, lrow = 0.f;

    for (int kt = 0; kt <= qt; kt++) {
        __syncthreads();
        {   int r = tid >> 2, q4 = tid & 3;
            #pragma unroll
            for (int ii = 0; ii < 4; ii++) {
                int c = (q4 + ii*4)*4;
                *(float4*)&Ks[r*TPAD + c] =
                    *(const float4*)(kbase + (size_t)(kt*64 + r)*QKV_LD + c);
                float4 vv = *(const float4*)(vbase + (size_t)(kt*64 + r)*QKV_LD + c);
                Vt[(c+0)*TPAD + r] = vv.x;
                Vt[(c+1)*TPAD + r] = vv.y;
                Vt[(c+2)*TPAD + r] = vv.z;
                Vt[(c+3)*TPAD + r] = vv.w;
            }
        }
        __syncthreads();

        float acc[4][4];
        #pragma unroll
        for (int i=0;i<4;i++)
            #pragma unroll
            for (int j=0;j<4;j++) acc[i][j]=0.f;
        #pragma unroll
        for (int d0 = 0; d0 < 64; d0 += 4) {
            float4 qa[4], kb[4];
            #pragma unroll
            for (int i=0;i<4;i++) qa[i] = *(const float4*)&Qs[(rg*4+i)*TPAD + d0];
            #pragma unroll
            for (int j=0;j<4;j++) kb[j] = *(const float4*)&Ks[(cg*4+j)*TPAD + d0];
            #pragma unroll
            for (int i=0;i<4;i++)
                #pragma unroll
                for (int j=0;j<4;j++)
                    acc[i][j] += qa[i].x*kb[j].x + qa[i].y*kb[j].y
                               + qa[i].z*kb[j].z + qa[i].w*kb[j].w;
        }
        bool diag = (kt == qt);
        #pragma unroll
        for (int i=0;i<4;i++) {
            int r = rg*4 + i;
            #pragma unroll
            for (int j=0;j<4;j++) {
                int c = cg*4 + j;
                float s = acc[i][j]*0.125f;
                if (diag && ((c>>3) > (r>>3))) s = -1e30f;
                Ps[r*TPAD + c] = s;
            }
        }
        __syncthreads();

        if (tid < 64) {
            float* row = &Ps[tid*TPAD];
            float mx = mrow;
            #pragma unroll 8
            for (int c=0;c<64;c++) mx = fmaxf(mx, row[c]);
            float al = __expf(mrow - mx);
            float sum = 0.f;
            #pragma unroll 8
            for (int c=0;c<64;c++) { float p = __expf(row[c]-mx); row[c]=p; sum+=p; }
            mrow = mx;
            lrow = lrow*al + sum;
            s_alpha[tid] = al;
        }
        __syncthreads();

        float av[4];
        #pragma unroll
        for (int i=0;i<4;i++) av[i] = s_alpha[rg*4+i];
        #pragma unroll
        for (int i=0;i<4;i++)
            #pragma unroll
            for (int j=0;j<4;j++) o[i][j] *= av[i];
        #pragma unroll
        for (int k0 = 0; k0 < 64; k0 += 4) {
            float4 pa[4], vb[4];
            #pragma unroll
            for (int i=0;i<4;i++) pa[i] = *(const float4*)&Ps[(rg*4+i)*TPAD + k0];
            #pragma unroll
            for (int j=0;j<4;j++) vb[j] = *(const float4*)&Vt[(cg*4+j)*TPAD + k0];
            #pragma unroll
            for (int i=0;i<4;i++)
                #pragma unroll
                for (int j=0;j<4;j++)
                    o[i][j] += pa[i].x*vb[j].x + pa[i].y*vb[j].y
                             + pa[i].z*vb[j].z + pa[i].w*vb[j].w;
        }
    }
    __syncthreads();
    if (tid < 64) s_linv[tid] = 1.f / lrow;
    __syncthreads();
    #pragma unroll
    for (int i=0;i<4;i++) {
        float li = s_linv[rg*4+i];
        size_t ro = ((size_t)b*SEQL + qt*64 + rg*4 + i)*DIMN + h*64 + cg*4;
        float4 ov;
        ov.x = o[i][0]*li; ov.y = o[i][1]*li; ov.z = o[i][2]*li; ov.w = o[i][3]*li;
        *(float4*)&outp[ro] = ov;
    }
}

/* ---------------- host launcher ------------------------------------------ */
extern "C" void kernel_launch(void* const* d_in, const int* in_sizes, int n_in,
                              void* d_out, int out_size) {
    const float *x,*vec,*wq,*wk,*wv,*wo,*w1,*w2,*w3,*maw,*mab,*mfw,*mfb,*n1,*n2,*fc,*fs;
    if (in_sizes[2] == 32768) {                   /* reference-argument order */
        x  =(const float*)d_in[0];  vec=(const float*)d_in[1];
        fc =(const float*)d_in[2];  fs =(const float*)d_in[3];
        wq =(const float*)d_in[4];  wk =(const float*)d_in[5];
        wv =(const float*)d_in[6];  wo =(const float*)d_in[7];
        w1 =(const float*)d_in[8];  w2 =(const float*)d_in[9];
        w3 =(const float*)d_in[10];
        maw=(const float*)d_in[11]; mab=(const float*)d_in[12];
        mfw=(const float*)d_in[13]; mfb=(const float*)d_in[14];
        n1 =(const float*)d_in[15]; n2 =(const float*)d_in[16];
    } else {                                      /* setup_inputs dict order */
        x  =(const float*)d_in[0];  vec=(const float*)d_in[1];
        wq =(const float*)d_in[2];  wk =(const float*)d_in[3];
        wv =(const float*)d_in[4];  wo =(const float*)d_in[5];
        w1 =(const float*)d_in[6];  w2 =(const float*)d_in[7];
        w3 =(const float*)d_in[8];
        maw=(const float*)d_in[9];  mab=(const float*)d_in[10];
        mfw=(const float*)d_in[11]; mfb=(const float*)d_in[12];
        n1 =(const float*)d_in[13]; n2 =(const float*)d_in[14];
        fc =(const float*)d_in[15]; fs =(const float*)d_in[16];
    }
    float* out = (float*)d_out;

    float *p_sv,*p_ma,*p_mf,*p_xn,*p_qkv,*p_attn,*p_h,*p_hn,*p_g1,*p_g3;
    cudaGetSymbolAddress((void**)&p_sv,  g_silu_vec);
    cudaGetSymbolAddress((void**)&p_ma,  g_mod_a);
    cudaGetSymbolAddress((void**)&p_mf,  g_mod_f);
    cudaGetSymbolAddress((void**)&p_xn,  g_xn);
    cudaGetSymbolAddress((void**)&p_qkv, g_qkv);
    cudaGetSymbolAddress((void**)&p_attn,g_attn);
    cudaGetSymbolAddress((void**)&p_h,   g_h);
    cudaGetSymbolAddress((void**)&p_hn,  g_hn);
    cudaGetSymbolAddress((void**)&p_g1,  g_g1);
    cudaGetSymbolAddress((void**)&p_g3,  g_g3);

    cudaFuncSetAttribute(attn_kernel,
                         cudaFuncAttributeMaxDynamicSharedMemorySize, ATT_SMEM);

    /* 1. silu(vec): 512*1024 elems / 4 / 256 = 512 blocks */
    silu_kernel<<<512, 256>>>(vec, p_sv);

    /* 2. modulation GEMMs (M=512, N=3072, K=1024) + bias */
    gemm_nt<1><<<dim3(48,4), 256>>>(p_sv,DIMN, maw,DIMN, p_ma,3*DIMN, DIMN,
                                    mab, nullptr,0, nullptr,0);
    gemm_nt<1><<<dim3(48,4), 256>>>(p_sv,DIMN, mfw,DIMN, p_mf,3*DIMN, DIMN,
                                    mfb, nullptr,0, nullptr,0);

    /* 3. xn = rmsnorm(x)*(1+scale)+shift */
    rmsnorm_mod_kernel<<<NTOK, 256>>>(x, n1, p_ma, p_xn);

    /* 4. QKV GEMMs into fused (4096 x 1536) buffer */
    gemm_nt<0><<<dim3(16,32), 256>>>(p_xn,DIMN, wq,DIMN, p_qkv,      QKV_LD, DIMN,
                                     nullptr, nullptr,0, nullptr,0);
    gemm_nt<0><<<dim3(4,32),  256>>>(p_xn,DIMN, wk,DIMN, p_qkv+1024, QKV_LD, DIMN,
                                     nullptr, nullptr,0, nullptr,0);
    gemm_nt<0><<<dim3(4,32),  256>>>(p_xn,DIMN, wv,DIMN, p_qkv+1280, QKV_LD, DIMN,
                                     nullptr, nullptr,0, nullptr,0);

    /* 5. RoPE on q + k: 4096 tokens * 20 heads * 32 pairs / 256 */
    rope_kernel<<<10240, 256>>>(p_qkv, fc, fs);

    /* 6. block-causal attention */
    attn_kernel<<<dim3(16,16,BATCHN), 256, ATT_SMEM>>>(p_qkv, p_attn);

    /* 7. h = x + gate_a * (attn @ wo^T) */
    gemm_nt<2><<<dim3(16,32), 256>>>(p_attn,DIMN, wo,DIMN, p_h,DIMN, DIMN,
                                     nullptr, x,DIMN, p_ma, 2*DIMN);

    /* 8. hn = rmsnorm(h)*(1+scale_f)+shift_f */
    rmsnorm_mod_kernel<<<NTOK, 256>>>(p_h, n2, p_mf, p_hn);

    /* 9. FFN up projections */
    gemm_nt<0><<<dim3(16,32), 256>>>(p_hn,DIMN, w1,DIMN, p_g1,DIMN, DIMN,
                                     nullptr, nullptr,0, nullptr,0);
    gemm_nt<0><<<dim3(16,32), 256>>>(p_hn,DIMN, w3,DIMN, p_g3,DIMN, DIMN,
                                     nullptr, nullptr,0, nullptr,0);

    /* 10. g1 = silu(g1) * g3 : 4M elems / 4 / 256 = 4096 blocks */
    swiglu_kernel<<<4096, 256>>>(p_g1, p_g3);

    /* 11. out = h + gate_f * (g1 @ w2^T) */
    gemm_nt<2><<<dim3(16,32), 256>>>(p_g1,DIMN, w2,DIMN, out,DIMN, DIMN,
                                     nullptr, p_h,DIMN, p_mf, 2*DIMN);
}

// round 5
// speedup vs baseline: 1.1309x; 1.1309x over previous
#include <cuda_runtime.h>
#include <cuda_bf16.h>
#include <mma.h>
#include <math.h>

using namespace nvcuda;

#define DIMN   1024
#define SEQL   1024
#define BATCHN 4
#define NTOK   (BATCHN*SEQL)     /* 4096 */
#define NBLK   (BATCHN*128)      /* 512 tokens of vec */
#define QKV_LD 1536
#define EPSV   1e-6f

/* ---------------- scratch (device globals: no allocation allowed) -------- */
__device__ float g_silu_vec[NBLK*DIMN];
__device__ float g_mod_a[NBLK*3*DIMN];
__device__ float g_mod_f[NBLK*3*DIMN];
__device__ float g_xn[NTOK*DIMN];
__device__ float g_qkv[NTOK*QKV_LD];
__device__ float g_attn[NTOK*DIMN];
__device__ float g_h[NTOK*DIMN];
__device__ float g_hn[NTOK*DIMN];
__device__ float g_g1[NTOK*DIMN];
__device__ float g_g3[NTOK*DIMN];

/* ---------------- elementwise kernels ------------------------------------ */
__global__ __launch_bounds__(256) void silu_kernel(const float* __restrict__ in,
                                                   float* __restrict__ out) {
    int i = blockIdx.x * 256 + threadIdx.x;
    float4 v = ((const float4*)in)[i];
    float4 o;
    o.x = v.x / (1.f + __expf(-v.x));
    o.y = v.y / (1.f + __expf(-v.y));
    o.z = v.z / (1.f + __expf(-v.z));
    o.w = v.w / (1.f + __expf(-v.w));
    ((float4*)out)[i] = o;
}

__global__ __launch_bounds__(256) void swiglu_kernel(float* __restrict__ g1,
                                                     const float* __restrict__ g3) {
    int i = blockIdx.x * 256 + threadIdx.x;
    float4 a = ((float4*)g1)[i];
    float4 b = ((const float4*)g3)[i];
    float4 o;
    o.x = (a.x / (1.f + __expf(-a.x))) * b.x;
    o.y = (a.y / (1.f + __expf(-a.y))) * b.y;
    o.z = (a.z / (1.f + __expf(-a.z))) * b.z;
    o.w = (a.w / (1.f + __expf(-a.w))) * b.w;
    ((float4*)g1)[i] = o;
}

/* rmsnorm + adaLN modulate: out = rms(x)*w*(1+scale) + shift                */
__global__ __launch_bounds__(256) void rmsnorm_mod_kernel(
    const float* __restrict__ X, const float* __restrict__ w,
    const float* __restrict__ mod, float* __restrict__ out) {
    int m = blockIdx.x;
    int tid = threadIdx.x;
    float4 v = ((const float4*)(X + (size_t)m*DIMN))[tid];
    float ss = v.x*v.x + v.y*v.y + v.z*v.z + v.w*v.w;
    #pragma unroll
    for (int o = 16; o; o >>= 1) ss += __shfl_xor_sync(0xffffffffu, ss, o);
    __shared__ float red[8];
    if ((tid & 31) == 0) red[tid >> 5] = ss;
    __syncthreads();
    float tot = red[0]+red[1]+red[2]+red[3]+red[4]+red[5]+red[6]+red[7];
    float rms = rsqrtf(tot * (1.f/DIMN) + EPSV);
    const float* mrow = mod + (size_t)(m >> 3) * (3*DIMN);
    float4 sh = *(const float4*)(mrow + tid*4);
    float4 sc = *(const float4*)(mrow + DIMN + tid*4);
    float4 wv = ((const float4*)w)[tid];
    float4 o;
    o.x = v.x*rms*wv.x*(1.f+sc.x) + sh.x;
    o.y = v.y*rms*wv.y*(1.f+sc.y) + sh.y;
    o.z = v.z*rms*wv.z*(1.f+sc.z) + sh.z;
    o.w = v.w*rms*wv.w*(1.f+sc.w) + sh.w;
    ((float4*)(out + (size_t)m*DIMN))[tid] = o;
}

/* interleaved RoPE on q (16 heads) + k (4 heads) inside the qkv buffer      */
__global__ __launch_bounds__(256) void rope_kernel(float* __restrict__ qkv,
                                                   const float* __restrict__ cosb,
                                                   const float* __restrict__ sinb) {
    int id = blockIdx.x * 256 + threadIdx.x;
    int d  = id & 31;  id >>= 5;
    int hh = id % 20;  int tg = id / 20;
    int col = (hh < 16) ? hh*64 : 1024 + (hh-16)*64;
    float* p = qkv + (size_t)tg*QKV_LD + col + 2*d;
    int t = tg & (SEQL-1);
    float c = cosb[t*32 + d], s = sinb[t*32 + d];
    float x1 = p[0], x2 = p[1];
    p[0] = x1*c - x2*s;
    p[1] = x1*s + x2*c;
}

/* ---------------- TF32 tensor-core GEMM: C(M,N) = A(M,K) @ B(N,K)^T ------- */
/* BM=128, BN=64, BK=16.  8 warps in 4x2 grid; each warp 32x32 = 2x2 wmma    */
/* m16n16k8 tf32 tiles.  Double-buffered smem; C staged through reused smem. */
#define BM 128
#define BN 64
#define BK 16
#define KPAD 20                  /* 16 + 4 pad, keeps 16B alignment */
#define CPAD 68

/* smem layout (floats):
     A buffers: [0 .. 5120)      = 2 * 128 * 20
     B buffers: [5120 .. 7680)   = 2 *  64 * 20
     C staging: [0 .. 8704)      = 128 * 68   (reused after main loop)       */
#define SM_FLOATS 8704
#define BS_OFF 5120

/* EPI 0: C = acc ; EPI 1: C = acc + bias[n]
   EPI 2: C = resid[m,n] + mod[(m>>3)*3072 + goff + n] * acc                  */
template<int EPI>
__global__ __launch_bounds__(256) void gemm_nt(
    const float* __restrict__ A, int lda,
    const float* __restrict__ B, int ldb,
    float* __restrict__ C, int ldc,
    int K,
    const float* __restrict__ bias,
    const float* __restrict__ resid, int ldr,
    const float* __restrict__ mod, int goff) {
    __shared__ float sm[SM_FLOATS];
    int tid = threadIdx.x;
    int wid = tid >> 5;
    int wm = wid >> 1, wn = wid & 1;        /* 4x2 warp grid */
    int m0 = blockIdx.y * BM, n0 = blockIdx.x * BN;
    const float* Ag = A + (size_t)m0 * lda;
    const float* Bg = B + (size_t)n0 * ldb;

    /* preload tile 0 */
    {
        #pragma unroll
        for (int i = 0; i < 2; i++) {
            int idx = tid + i*256, r = idx >> 2, kq = (idx & 3)*4;
            float4 v = *(const float4*)(Ag + (size_t)r*lda + kq);
            *(float4*)&sm[r*KPAD + kq] = v;
        }
        int r = tid >> 2, kq = (tid & 3)*4;
        float4 v = *(const float4*)(Bg + (size_t)r*ldb + kq);
        *(float4*)&sm[BS_OFF + r*KPAD + kq] = v;
    }
    __syncthreads();

    wmma::fragment<wmma::accumulator, 16,16,8, float> c[2][2];
    #pragma unroll
    for (int i=0;i<2;i++)
        #pragma unroll
        for (int j=0;j<2;j++) wmma::fill_fragment(c[i][j], 0.f);

    int nk = K / BK;
    float4 ra[2], rb;
    for (int kt = 0; kt < nk; kt++) {
        int cur = kt & 1;
        if (kt + 1 < nk) {
            int k0 = (kt+1)*BK;
            #pragma unroll
            for (int i = 0; i < 2; i++) {
                int idx = tid + i*256, r = idx >> 2, kq = (idx & 3)*4;
                ra[i] = *(const float4*)(Ag + (size_t)r*lda + k0 + kq);
            }
            int r = tid >> 2, kq = (tid & 3)*4;
            rb = *(const float4*)(Bg + (size_t)r*ldb + k0 + kq);
        }
        const float* Ab = &sm[cur*2560];
        const float* Bb = &sm[BS_OFF + cur*1280];
        #pragma unroll
        for (int kk = 0; kk < BK; kk += 8) {
            wmma::fragment<wmma::matrix_a, 16,16,8, wmma::precision::tf32, wmma::row_major> a[2];
            wmma::fragment<wmma::matrix_b, 16,16,8, wmma::precision::tf32, wmma::col_major> b[2];
            #pragma unroll
            for (int i=0;i<2;i++) {
                wmma::load_matrix_sync(a[i], Ab + (wm*32 + i*16)*KPAD + kk, KPAD);
                #pragma unroll
                for (int e=0;e<a[i].num_elements;e++)
                    a[i].x[e] = wmma::__float_to_tf32(a[i].x[e]);
            }
            #pragma unroll
            for (int j=0;j<2;j++) {
                wmma::load_matrix_sync(b[j], Bb + (wn*32 + j*16)*KPAD + kk, KPAD);
                #pragma unroll
                for (int e=0;e<b[j].num_elements;e++)
                    b[j].x[e] = wmma::__float_to_tf32(b[j].x[e]);
            }
            #pragma unroll
            for (int i=0;i<2;i++)
                #pragma unroll
                for (int j=0;j<2;j++)
                    wmma::mma_sync(c[i][j], a[i], b[j], c[i][j]);
        }
        if (kt + 1 < nk) {
            int nxt = cur ^ 1;
            #pragma unroll
            for (int i = 0; i < 2; i++) {
                int idx = tid + i*256, r = idx >> 2, kq = (idx & 3)*4;
                *(float4*)&sm[nxt*2560 + r*KPAD + kq] = ra[i];
            }
            int r = tid >> 2, kq = (tid & 3)*4;
            *(float4*)&sm[BS_OFF + nxt*1280 + r*KPAD + kq] = rb;
        }
        __syncthreads();
    }

    /* stage accumulators through smem (reuses A/B region; loop ended with
       a __syncthreads so all fragment reads are complete)                   */
    #pragma unroll
    for (int i=0;i<2;i++)
        #pragma unroll
        for (int j=0;j<2;j++)
            wmma::store_matrix_sync(&sm[(wm*32 + i*16)*CPAD + wn*32 + j*16],
                                    c[i][j], CPAD, wmma::mem_row_major);
    __syncthreads();

    /* fused epilogue: 128x64 floats = 2048 float4, 8 per thread */
    #pragma unroll
    for (int it = 0; it < 8; it++) {
        int idx = it*256 + tid;
        int row = idx >> 4, c4 = (idx & 15)*4;
        float4 acc = *(const float4*)&sm[row*CPAD + c4];
        int m = m0 + row, n = n0 + c4;
        float4 out;
        if (EPI == 0) {
            out = acc;
        } else if (EPI == 1) {
            float4 bv = *(const float4*)(bias + n);
            out.x=acc.x+bv.x; out.y=acc.y+bv.y; out.z=acc.z+bv.z; out.w=acc.w+bv.w;
        } else {
            float4 gv = *(const float4*)(mod + (size_t)(m>>3)*(3*DIMN) + goff + n);
            float4 rv = *(const float4*)(resid + (size_t)m*ldr + n);
            out.x = rv.x + gv.x*acc.x;
            out.y = rv.y + gv.y*acc.y;
            out.z = rv.z + gv.z*acc.z;
            out.w = rv.w + gv.w*acc.w;
        }
        *(float4*)(C + (size_t)m*ldc + n) = out;
    }
}

/* ---------------- block-causal flash attention ---------------------------- */
#define TPAD 68
#define ATT_SMEM (4*64*TPAD*4 + 2*64*4)

__global__ __launch_bounds__(256) void attn_kernel(const float* __restrict__ qkv,
                                                   float* __restrict__ outp) {
    extern __shared__ float sm[];
    float* Qs = sm;
    float* Ks = Qs + 64*TPAD;
    float* Vt = Ks + 64*TPAD;
    float* Ps = Vt + 64*TPAD;
    float* s_alpha = Ps + 64*TPAD;
    float* s_linv  = s_alpha + 64;

    int qt = blockIdx.x, h = blockIdx.y, b = blockIdx.z;
    int tid = threadIdx.x;
    int rg = tid >> 4, cg = tid & 15;

    const float* qbase = qkv + (size_t)b*SEQL*QKV_LD + h*64;
    const float* kbase = qkv + (size_t)b*SEQL*QKV_LD + 1024 + (h>>2)*64;
    const float* vbase = kbase + 256;

    {   int r = tid >> 2, q4 = tid & 3;
        #pragma unroll
        for (int ii = 0; ii < 4; ii++) {
            int c = (q4 + ii*4)*4;
            *(float4*)&Qs[r*TPAD + c] =
                *(const float4*)(qbase + (size_t)(qt*64 + r)*QKV_LD + c);
        }
    }
    float o[4][4];
    #pragma unroll
    for (int i=0;i<4;i++)
        #pragma unroll
        for (int j=0;j<4;j++) o[i][j]=0.f;
    float mrow = -1e30f, lrow = 0.f;

    for (int kt = 0; kt <= qt; kt++) {
        __syncthreads();
        {   int r = tid >> 2, q4 = tid & 3;
            #pragma unroll
            for (int ii = 0; ii < 4; ii++) {
                int c = (q4 + ii*4)*4;
                *(float4*)&Ks[r*TPAD + c] =
                    *(const float4*)(kbase + (size_t)(kt*64 + r)*QKV_LD + c);
                float4 vv = *(const float4*)(vbase + (size_t)(kt*64 + r)*QKV_LD + c);
                Vt[(c+0)*TPAD + r] = vv.x;
                Vt[(c+1)*TPAD + r] = vv.y;
                Vt[(c+2)*TPAD + r] = vv.z;
                Vt[(c+3)*TPAD + r] = vv.w;
            }
        }
        __syncthreads();

        float acc[4][4];
        #pragma unroll
        for (int i=0;i<4;i++)
            #pragma unroll
            for (int j=0;j<4;j++) acc[i][j]=0.f;
        #pragma unroll
        for (int d0 = 0; d0 < 64; d0 += 4) {
            float4 qa[4], kb[4];
            #pragma unroll
            for (int i=0;i<4;i++) qa[i] = *(const float4*)&Qs[(rg*4+i)*TPAD + d0];
            #pragma unroll
            for (int j=0;j<4;j++) kb[j] = *(const float4*)&Ks[(cg*4+j)*TPAD + d0];
            #pragma unroll
            for (int i=0;i<4;i++)
                #pragma unroll
                for (int j=0;j<4;j++)
                    acc[i][j] += qa[i].x*kb[j].x + qa[i].y*kb[j].y
                               + qa[i].z*kb[j].z + qa[i].w*kb[j].w;
        }
        bool diag = (kt == qt);
        #pragma unroll
        for (int i=0;i<4;i++) {
            int r = rg*4 + i;
            #pragma unroll
            for (int j=0;j<4;j++) {
                int c = cg*4 + j;
                float s = acc[i][j]*0.125f;
                if (diag && ((c>>3) > (r>>3))) s = -1e30f;
                Ps[r*TPAD + c] = s;
            }
        }
        __syncthreads();

        if (tid < 64) {
            float* row = &Ps[tid*TPAD];
            float mx = mrow;
            #pragma unroll 8
            for (int c=0;c<64;c++) mx = fmaxf(mx, row[c]);
            float al = __expf(mrow - mx);
            float sum = 0.f;
            #pragma unroll 8
            for (int c=0;c<64;c++) { float p = __expf(row[c]-mx); row[c]=p; sum+=p; }
            mrow = mx;
            lrow = lrow*al + sum;
            s_alpha[tid] = al;
        }
        __syncthreads();

        float av[4];
        #pragma unroll
        for (int i=0;i<4;i++) av[i] = s_alpha[rg*4+i];
        #pragma unroll
        for (int i=0;i<4;i++)
            #pragma unroll
            for (int j=0;j<4;j++) o[i][j] *= av[i];
        #pragma unroll
        for (int k0 = 0; k0 < 64; k0 += 4) {
            float4 pa[4], vb[4];
            #pragma unroll
            for (int i=0;i<4;i++) pa[i] = *(const float4*)&Ps[(rg*4+i)*TPAD + k0];
            #pragma unroll
            for (int j=0;j<4;j++) vb[j] = *(const float4*)&Vt[(cg*4+j)*TPAD + k0];
            #pragma unroll
            for (int i=0;i<4;i++)
                #pragma unroll
                for (int j=0;j<4;j++)
                    o[i][j] += pa[i].x*vb[j].x + pa[i].y*vb[j].y
                             + pa[i].z*vb[j].z + pa[i].w*vb[j].w;
        }
    }
    __syncthreads();
    if (tid < 64) s_linv[tid] = 1.f / lrow;
    __syncthreads();
    #pragma unroll
    for (int i=0;i<4;i++) {
        float li = s_linv[rg*4+i];
        size_t ro = ((size_t)b*SEQL + qt*64 + rg*4 + i)*DIMN + h*64 + cg*4;
        float4 ov;
        ov.x = o[i][0]*li; ov.y = o[i][1]*li; ov.z = o[i][2]*li; ov.w = o[i][3]*li;
        *(float4*)&outp[ro] = ov;
    }
}

/* ---------------- host launcher ------------------------------------------ */
extern "C" void kernel_launch(void* const* d_in, const int* in_sizes, int n_in,
                              void* d_out, int out_size) {
    const float *x,*vec,*wq,*wk,*wv,*wo,*w1,*w2,*w3,*maw,*mab,*mfw,*mfb,*n1,*n2,*fc,*fs;
    if (in_sizes[2] == 32768) {                   /* reference-argument order */
        x  =(const float*)d_in[0];  vec=(const float*)d_in[1];
        fc =(const float*)d_in[2];  fs =(const float*)d_in[3];
        wq =(const float*)d_in[4];  wk =(const float*)d_in[5];
        wv =(const float*)d_in[6];  wo =(const float*)d_in[7];
        w1 =(const float*)d_in[8];  w2 =(const float*)d_in[9];
        w3 =(const float*)d_in[10];
        maw=(const float*)d_in[11]; mab=(const float*)d_in[12];
        mfw=(const float*)d_in[13]; mfb=(const float*)d_in[14];
        n1 =(const float*)d_in[15]; n2 =(const float*)d_in[16];
    } else {                                      /* setup_inputs dict order */
        x  =(const float*)d_in[0];  vec=(const float*)d_in[1];
        wq =(const float*)d_in[2];  wk =(const float*)d_in[3];
        wv =(const float*)d_in[4];  wo =(const float*)d_in[5];
        w1 =(const float*)d_in[6];  w2 =(const float*)d_in[7];
        w3 =(const float*)d_in[8];
        maw=(const float*)d_in[9];  mab=(const float*)d_in[10];
        mfw=(const float*)d_in[11]; mfb=(const float*)d_in[12];
        n1 =(const float*)d_in[13]; n2 =(const float*)d_in[14];
        fc =(const float*)d_in[15]; fs =(const float*)d_in[16];
    }
    float* out = (float*)d_out;

    float *p_sv,*p_ma,*p_mf,*p_xn,*p_qkv,*p_attn,*p_h,*p_hn,*p_g1,*p_g3;
    cudaGetSymbolAddress((void**)&p_sv,  g_silu_vec);
    cudaGetSymbolAddress((void**)&p_ma,  g_mod_a);
    cudaGetSymbolAddress((void**)&p_mf,  g_mod_f);
    cudaGetSymbolAddress((void**)&p_xn,  g_xn);
    cudaGetSymbolAddress((void**)&p_qkv, g_qkv);
    cudaGetSymbolAddress((void**)&p_attn,g_attn);
    cudaGetSymbolAddress((void**)&p_h,   g_h);
    cudaGetSymbolAddress((void**)&p_hn,  g_hn);
    cudaGetSymbolAddress((void**)&p_g1,  g_g1);
    cudaGetSymbolAddress((void**)&p_g3,  g_g3);

    cudaFuncSetAttribute(attn_kernel,
                         cudaFuncAttributeMaxDynamicSharedMemorySize, ATT_SMEM);

    /* 1. silu(vec) */
    silu_kernel<<<512, 256>>>(vec, p_sv);

    /* 2. modulation GEMMs (M=512, N=3072, K=1024) + bias */
    gemm_nt<1><<<dim3(48,4), 256>>>(p_sv,DIMN, maw,DIMN, p_ma,3*DIMN, DIMN,
                                    mab, nullptr,0, nullptr,0);
    gemm_nt<1><<<dim3(48,4), 256>>>(p_sv,DIMN, mfw,DIMN, p_mf,3*DIMN, DIMN,
                                    mfb, nullptr,0, nullptr,0);

    /* 3. xn = rmsnorm(x)*(1+scale)+shift */
    rmsnorm_mod_kernel<<<NTOK, 256>>>(x, n1, p_ma, p_xn);

    /* 4. QKV GEMMs into fused (4096 x 1536) buffer */
    gemm_nt<0><<<dim3(16,32), 256>>>(p_xn,DIMN, wq,DIMN, p_qkv,      QKV_LD, DIMN,
                                     nullptr, nullptr,0, nullptr,0);
    gemm_nt<0><<<dim3(4,32),  256>>>(p_xn,DIMN, wk,DIMN, p_qkv+1024, QKV_LD, DIMN,
                                     nullptr, nullptr,0, nullptr,0);
    gemm_nt<0><<<dim3(4,32),  256>>>(p_xn,DIMN, wv,DIMN, p_qkv+1280, QKV_LD, DIMN,
                                     nullptr, nullptr,0, nullptr,0);

    /* 5. RoPE on q + k */
    rope_kernel<<<10240, 256>>>(p_qkv, fc, fs);

    /* 6. block-causal attention */
    attn_kernel<<<dim3(16,16,BATCHN), 256, ATT_SMEM>>>(p_qkv, p_attn);

    /* 7. h = x + gate_a * (attn @ wo^T) */
    gemm_nt<2><<<dim3(16,32), 256>>>(p_attn,DIMN, wo,DIMN, p_h,DIMN, DIMN,
                                     nullptr, x,DIMN, p_ma, 2*DIMN);

    /* 8. hn = rmsnorm(h)*(1+scale_f)+shift_f */
    rmsnorm_mod_kernel<<<NTOK, 256>>>(p_h, n2, p_mf, p_hn);

    /* 9. FFN up projections */
    gemm_nt<0><<<dim3(16,32), 256>>>(p_hn,DIMN, w1,DIMN, p_g1,DIMN, DIMN,
                                     nullptr, nullptr,0, nullptr,0);
    gemm_nt<0><<<dim3(16,32), 256>>>(p_hn,DIMN, w3,DIMN, p_g3,DIMN, DIMN,
                                     nullptr, nullptr,0, nullptr,0);

    /* 10. g1 = silu(g1) * g3 */
    swiglu_kernel<<<4096, 256>>>(p_g1, p_g3);

    /* 11. out = h + gate_f * (g1 @ w2^T) */
    gemm_nt<2><<<dim3(16,32), 256>>>(p_g1,DIMN, w2,DIMN, out,DIMN, DIMN,
                                     nullptr, p_h,DIMN, p_mf, 2*DIMN);
}

// round 7
// speedup vs baseline: 1.5088x; 1.3341x over previous
#include <cuda_runtime.h>
#include <cuda_bf16.h>
#include <math.h>
#include <stdint.h>

#define DIMN   1024
#define SEQL   1024
#define BATCHN 4
#define NTOK   (BATCHN*SEQL)     /* 4096 */
#define NBLK   (BATCHN*128)      /* 512 tokens of vec */
#define QKV_LD 1536
#define EPSV   1e-6f

/* ---------------- scratch (device globals: no allocation allowed) -------- */
__device__ float g_silu_vec[NBLK*DIMN];
__device__ float g_mod_a[NBLK*3*DIMN];
__device__ float g_mod_f[NBLK*3*DIMN];
__device__ float g_xn[NTOK*DIMN];
__device__ float g_qkv[NTOK*QKV_LD];
__device__ float g_attn[NTOK*DIMN];
__device__ float g_h[NTOK*DIMN];
__device__ float g_hn[NTOK*DIMN];
__device__ float g_g1[NTOK*DIMN];
__device__ float g_g3[NTOK*DIMN];

__device__ __forceinline__ uint32_t f2tf32(float f) {
    uint32_t u;
    asm("cvt.rna.tf32.f32 %0, %1;" : "=r"(u) : "f"(f));
    return u;
}
/* word-index of element (r,c) in a 128x32-word tile, 128B-group XOR swizzle */
__device__ __forceinline__ int swaddr(int r, int c) {
    return r*32 + ((((c >> 2) ^ (r & 7)) << 2) | (c & 3));
}
__device__ __forceinline__ void mma_tf32_16x8x8(float* c, const uint32_t* a,
                                                const uint32_t* b) {
    asm volatile(
        "mma.sync.aligned.m16n8k8.row.col.f32.tf32.tf32.f32 "
        "{%0,%1,%2,%3}, {%4,%5,%6,%7}, {%8,%9}, {%0,%1,%2,%3};"
        : "+f"(c[0]), "+f"(c[1]), "+f"(c[2]), "+f"(c[3])
        : "r"(a[0]), "r"(a[1]), "r"(a[2]), "r"(a[3]), "r"(b[0]), "r"(b[1]));
}

/* ---------------- TF32 mma.sync GEMM: C(M,N) = A(M,K) @ B(N,K)^T ---------- */
/* CTA 128x128x32; 8 warps in 4x2; warp tile 32x64 = 2x8 m16n8k8 fragments.  */
/* fp32 -> tf32 conversion happens ONCE at the smem store.                    */
#define GSMEM 65536   /* 2 x (128x32) u32 A  +  2 x (128x32) u32 B */

/* EPI 0: C = acc ; EPI 1: C = acc + bias[n]
   EPI 2: C = resid[m,n] + mod[(m>>3)*3072 + goff + n] * acc                  */
template<int EPI>
__global__ __launch_bounds__(256) void gemm_nt(
    const float* __restrict__ A, int lda,
    const float* __restrict__ B, int ldb,
    float* __restrict__ C, int ldc,
    int K,
    const float* __restrict__ bias,
    const float* __restrict__ resid, int ldr,
    const float* __restrict__ mod, int goff) {
    extern __shared__ uint32_t sw[];
    uint32_t* smA = sw;           /* 2 buffers x 4096 words */
    uint32_t* smB = sw + 8192;
    int tid = threadIdx.x, lane = tid & 31, wid = tid >> 5;
    int wm = wid >> 1, wn = wid & 1;
    int m0 = blockIdx.y*128, n0 = blockIdx.x*128;
    const float* Ag = A + (size_t)m0 * lda;
    const float* Bg = B + (size_t)n0 * ldb;
    int t4r = lane >> 2, t4c = lane & 3;

    /* preload stage 0: each thread 4 float4 of A and 4 of B */
    #pragma unroll
    for (int i = 0; i < 4; i++) {
        int e4 = tid + i*256;
        int r = e4 >> 3, g = e4 & 7;
        float4 va = *(const float4*)(Ag + (size_t)r*lda + g*4);
        float4 vb = *(const float4*)(Bg + (size_t)r*ldb + g*4);
        int off = r*32 + ((g ^ (r & 7)) << 2);
        *(uint4*)&smA[off] = make_uint4(f2tf32(va.x), f2tf32(va.y),
                                        f2tf32(va.z), f2tf32(va.w));
        *(uint4*)&smB[off] = make_uint4(f2tf32(vb.x), f2tf32(vb.y),
                                        f2tf32(vb.z), f2tf32(vb.w));
    }
    __syncthreads();

    float acc[2][8][4];
    #pragma unroll
    for (int mt=0;mt<2;mt++)
        #pragma unroll
        for (int nt=0;nt<8;nt++)
            #pragma unroll
            for (int e=0;e<4;e++) acc[mt][nt][e]=0.f;

    int nk = K >> 5;
    float4 ra[4], rb[4];
    for (int s = 0; s < nk; s++) {
        int cur = s & 1;
        if (s + 1 < nk) {
            int k0 = (s+1)*32;
            #pragma unroll
            for (int i = 0; i < 4; i++) {
                int e4 = tid + i*256;
                int r = e4 >> 3, g = e4 & 7;
                ra[i] = *(const float4*)(Ag + (size_t)r*lda + k0 + g*4);
                rb[i] = *(const float4*)(Bg + (size_t)r*ldb + k0 + g*4);
            }
        }
        const uint32_t* Ab = smA + cur*4096;
        const uint32_t* Bb = smB + cur*4096;
        #pragma unroll
        for (int kq = 0; kq < 32; kq += 8) {
            uint32_t af[2][4], bf[8][2];
            #pragma unroll
            for (int mt = 0; mt < 2; mt++) {
                int r0 = wm*32 + mt*16 + t4r;
                af[mt][0] = Ab[swaddr(r0,     kq + t4c)];
                af[mt][1] = Ab[swaddr(r0 + 8, kq + t4c)];
                af[mt][2] = Ab[swaddr(r0,     kq + 4 + t4c)];
                af[mt][3] = Ab[swaddr(r0 + 8, kq + 4 + t4c)];
            }
            #pragma unroll
            for (int nt = 0; nt < 8; nt++) {
                int n = wn*64 + nt*8 + t4r;
                bf[nt][0] = Bb[swaddr(n, kq + t4c)];
                bf[nt][1] = Bb[swaddr(n, kq + 4 + t4c)];
            }
            #pragma unroll
            for (int mt = 0; mt < 2; mt++)
                #pragma unroll
                for (int nt = 0; nt < 8; nt++)
                    mma_tf32_16x8x8(acc[mt][nt], af[mt], bf[nt]);
        }
        if (s + 1 < nk) {
            int nxt = cur ^ 1;
            #pragma unroll
            for (int i = 0; i < 4; i++) {
                int e4 = tid + i*256;
                int r = e4 >> 3, g = e4 & 7;
                int off = nxt*4096 + r*32 + ((g ^ (r & 7)) << 2);
                *(uint4*)&smA[off] = make_uint4(f2tf32(ra[i].x), f2tf32(ra[i].y),
                                                f2tf32(ra[i].z), f2tf32(ra[i].w));
                *(uint4*)&smB[off] = make_uint4(f2tf32(rb[i].x), f2tf32(rb[i].y),
                                                f2tf32(rb[i].z), f2tf32(rb[i].w));
            }
        }
        __syncthreads();
    }

    /* epilogue straight from fragments: float2 per (tile, half-row) */
    #pragma unroll
    for (int mt = 0; mt < 2; mt++) {
        int rb0 = m0 + wm*32 + mt*16 + t4r;
        #pragma unroll
        for (int h = 0; h < 2; h++) {
            int m = rb0 + h*8;
            #pragma unroll
            for (int nt = 0; nt < 8; nt++) {
                int n = n0 + wn*64 + nt*8 + 2*t4c;
                float2 a2 = make_float2(acc[mt][nt][2*h], acc[mt][nt][2*h+1]);
                float2 o;
                if (EPI == 0) {
                    o = a2;
                } else if (EPI == 1) {
                    const float2 bv = *(const float2*)(bias + n);
                    o.x = a2.x + bv.x; o.y = a2.y + bv.y;
                } else {
                    const float2 gv = *(const float2*)(mod + (size_t)(m>>3)*(3*DIMN) + goff + n);
                    const float2 rv = *(const float2*)(resid + (size_t)m*ldr + n);
                    o.x = rv.x + gv.x*a2.x;
                    o.y = rv.y + gv.y*a2.y;
                }
                *(float2*)(C + (size_t)m*ldc + n) = o;
            }
        }
    }
}

/* ---------------- elementwise kernels ------------------------------------ */
__global__ __launch_bounds__(256) void silu_kernel(const float* __restrict__ in,
                                                   float* __restrict__ out) {
    int i = blockIdx.x * 256 + threadIdx.x;
    float4 v = ((const float4*)in)[i];
    float4 o;
    o.x = v.x / (1.f + __expf(-v.x));
    o.y = v.y / (1.f + __expf(-v.y));
    o.z = v.z / (1.f + __expf(-v.z));
    o.w = v.w / (1.f + __expf(-v.w));
    ((float4*)out)[i] = o;
}

__global__ __launch_bounds__(256) void swiglu_kernel(float* __restrict__ g1,
                                                     const float* __restrict__ g3) {
    int i = blockIdx.x * 256 + threadIdx.x;
    float4 a = ((float4*)g1)[i];
    float4 b = ((const float4*)g3)[i];
    float4 o;
    o.x = (a.x / (1.f + __expf(-a.x))) * b.x;
    o.y = (a.y / (1.f + __expf(-a.y))) * b.y;
    o.z = (a.z / (1.f + __expf(-a.z))) * b.z;
    o.w = (a.w / (1.f + __expf(-a.w))) * b.w;
    ((float4*)g1)[i] = o;
}

__global__ __launch_bounds__(256) void rmsnorm_mod_kernel(
    const float* __restrict__ X, const float* __restrict__ w,
    const float* __restrict__ mod, float* __restrict__ out) {
    int m = blockIdx.x;
    int tid = threadIdx.x;
    float4 v = ((const float4*)(X + (size_t)m*DIMN))[tid];
    float ss = v.x*v.x + v.y*v.y + v.z*v.z + v.w*v.w;
    #pragma unroll
    for (int o = 16; o; o >>= 1) ss += __shfl_xor_sync(0xffffffffu, ss, o);
    __shared__ float red[8];
    if ((tid & 31) == 0) red[tid >> 5] = ss;
    __syncthreads();
    float tot = red[0]+red[1]+red[2]+red[3]+red[4]+red[5]+red[6]+red[7];
    float rms = rsqrtf(tot * (1.f/DIMN) + EPSV);
    const float* mrow = mod + (size_t)(m >> 3) * (3*DIMN);
    float4 sh = *(const float4*)(mrow + tid*4);
    float4 sc = *(const float4*)(mrow + DIMN + tid*4);
    float4 wv = ((const float4*)w)[tid];
    float4 o;
    o.x = v.x*rms*wv.x*(1.f+sc.x) + sh.x;
    o.y = v.y*rms*wv.y*(1.f+sc.y) + sh.y;
    o.z = v.z*rms*wv.z*(1.f+sc.z) + sh.z;
    o.w = v.w*rms*wv.w*(1.f+sc.w) + sh.w;
    ((float4*)(out + (size_t)m*DIMN))[tid] = o;
}

__global__ __launch_bounds__(256) void rope_kernel(float* __restrict__ qkv,
                                                   const float* __restrict__ cosb,
                                                   const float* __restrict__ sinb) {
    int id = blockIdx.x * 256 + threadIdx.x;
    int d  = id & 31;  id >>= 5;
    int hh = id % 20;  int tg = id / 20;
    int col = (hh < 16) ? hh*64 : 1024 + (hh-16)*64;
    float* p = qkv + (size_t)tg*QKV_LD + col + 2*d;
    int t = tg & (SEQL-1);
    float c = cosb[t*32 + d], s = sinb[t*32 + d];
    float x1 = p[0], x2 = p[1];
    p[0] = x1*c - x2*s;
    p[1] = x1*s + x2*c;
}

/* ---------------- block-causal flash attention ---------------------------- */
#define TPAD 68
#define ATT_SMEM (4*64*TPAD*4 + 2*64*4)

__global__ __launch_bounds__(256) void attn_kernel(const float* __restrict__ qkv,
                                                   float* __restrict__ outp) {
    extern __shared__ float sm[];
    float* Qs = sm;
    float* Ks = Qs + 64*TPAD;
    float* Vt = Ks + 64*TPAD;
    float* Ps = Vt + 64*TPAD;
    float* s_alpha = Ps + 64*TPAD;
    float* s_linv  = s_alpha + 64;

    int qt = blockIdx.x, h = blockIdx.y, b = blockIdx.z;
    int tid = threadIdx.x;
    int rg = tid >> 4, cg = tid & 15;

    const float* qbase = qkv + (size_t)b*SEQL*QKV_LD + h*64;
    const float* kbase = qkv + (size_t)b*SEQL*QKV_LD + 1024 + (h>>2)*64;
    const float* vbase = kbase + 256;

    {   int r = tid >> 2, q4 = tid & 3;
        #pragma unroll
        for (int ii = 0; ii < 4; ii++) {
            int c = (q4 + ii*4)*4;
            *(float4*)&Qs[r*TPAD + c] =
                *(const float4*)(qbase + (size_t)(qt*64 + r)*QKV_LD + c);
        }
    }
    float o[4][4];
    #pragma unroll
    for (int i=0;i<4;i++)
        #pragma unroll
        for (int j=0;j<4;j++) o[i][j]=0.f;
    float mrow = -1e30f, lrow = 0.f;

    for (int kt = 0; kt <= qt; kt++) {
        __syncthreads();
        {   int r = tid >> 2, q4 = tid & 3;
            #pragma unroll
            for (int ii = 0; ii < 4; ii++) {
                int c = (q4 + ii*4)*4;
                *(float4*)&Ks[r*TPAD + c] =
                    *(const float4*)(kbase + (size_t)(kt*64 + r)*QKV_LD + c);
                float4 vv = *(const float4*)(vbase + (size_t)(kt*64 + r)*QKV_LD + c);
                Vt[(c+0)*TPAD + r] = vv.x;
                Vt[(c+1)*TPAD + r] = vv.y;
                Vt[(c+2)*TPAD + r] = vv.z;
                Vt[(c+3)*TPAD + r] = vv.w;
            }
        }
        __syncthreads();

        float acc[4][4];
        #pragma unroll
        for (int i=0;i<4;i++)
            #pragma unroll
            for (int j=0;j<4;j++) acc[i][j]=0.f;
        #pragma unroll
        for (int d0 = 0; d0 < 64; d0 += 4) {
            float4 qa[4], kb[4];
            #pragma unroll
            for (int i=0;i<4;i++) qa[i] = *(const float4*)&Qs[(rg*4+i)*TPAD + d0];
            #pragma unroll
            for (int j=0;j<4;j++) kb[j] = *(const float4*)&Ks[(cg*4+j)*TPAD + d0];
            #pragma unroll
            for (int i=0;i<4;i++)
                #pragma unroll
                for (int j=0;j<4;j++)
                    acc[i][j] += qa[i].x*kb[j].x + qa[i].y*kb[j].y
                               + qa[i].z*kb[j].z + qa[i].w*kb[j].w;
        }
        bool diag = (kt == qt);
        #pragma unroll
        for (int i=0;i<4;i++) {
            int r = rg*4 + i;
            #pragma unroll
            for (int j=0;j<4;j++) {
                int c = cg*4 + j;
                float s = acc[i][j]*0.125f;
                if (diag && ((c>>3) > (r>>3))) s = -1e30f;
                Ps[r*TPAD + c] = s;
            }
        }
        __syncthreads();

        if (tid < 64) {
            float* row = &Ps[tid*TPAD];
            float mx = mrow;
            #pragma unroll 8
            for (int c=0;c<64;c++) mx = fmaxf(mx, row[c]);
            float al = __expf(mrow - mx);
            float sum = 0.f;
            #pragma unroll 8
            for (int c=0;c<64;c++) { float p = __expf(row[c]-mx); row[c]=p; sum+=p; }
            mrow = mx;
            lrow = lrow*al + sum;
            s_alpha[tid] = al;
        }
        __syncthreads();

        float av[4];
        #pragma unroll
        for (int i=0;i<4;i++) av[i] = s_alpha[rg*4+i];
        #pragma unroll
        for (int i=0;i<4;i++)
            #pragma unroll
            for (int j=0;j<4;j++) o[i][j] *= av[i];
        #pragma unroll
        for (int k0 = 0; k0 < 64; k0 += 4) {
            float4 pa[4], vb[4];
            #pragma unroll
            for (int i=0;i<4;i++) pa[i] = *(const float4*)&Ps[(rg*4+i)*TPAD + k0];
            #pragma unroll
            for (int j=0;j<4;j++) vb[j] = *(const float4*)&Vt[(cg*4+j)*TPAD + k0];
            #pragma unroll
            for (int i=0;i<4;i++)
                #pragma unroll
                for (int j=0;j<4;j++)
                    o[i][j] += pa[i].x*vb[j].x + pa[i].y*vb[j].y
                             + pa[i].z*vb[j].z + pa[i].w*vb[j].w;
        }
    }
    __syncthreads();
    if (tid < 64) s_linv[tid] = 1.f / lrow;
    __syncthreads();
    #pragma unroll
    for (int i=0;i<4;i++) {
        float li = s_linv[rg*4+i];
        size_t ro = ((size_t)b*SEQL + qt*64 + rg*4 + i)*DIMN + h*64 + cg*4;
        float4 ov;
        ov.x = o[i][0]*li; ov.y = o[i][1]*li; ov.z = o[i][2]*li; ov.w = o[i][3]*li;
        *(float4*)&outp[ro] = ov;
    }
}

/* ---------------- host launcher ------------------------------------------ */
extern "C" void kernel_launch(void* const* d_in, const int* in_sizes, int n_in,
                              void* d_out, int out_size) {
    const float *x,*vec,*wq,*wk,*wv,*wo,*w1,*w2,*w3,*maw,*mab,*mfw,*mfb,*n1,*n2,*fc,*fs;
    if (in_sizes[2] == 32768) {                   /* reference-argument order */
        x  =(const float*)d_in[0];  vec=(const float*)d_in[1];
        fc =(const float*)d_in[2];  fs =(const float*)d_in[3];
        wq =(const float*)d_in[4];  wk =(const float*)d_in[5];
        wv =(const float*)d_in[6];  wo =(const float*)d_in[7];
        w1 =(const float*)d_in[8];  w2 =(const float*)d_in[9];
        w3 =(const float*)d_in[10];
        maw=(const float*)d_in[11]; mab=(const float*)d_in[12];
        mfw=(const float*)d_in[13]; mfb=(const float*)d_in[14];
        n1 =(const float*)d_in[15]; n2 =(const float*)d_in[16];
    } else {                                      /* setup_inputs dict order */
        x  =(const float*)d_in[0];  vec=(const float*)d_in[1];
        wq =(const float*)d_in[2];  wk =(const float*)d_in[3];
        wv =(const float*)d_in[4];  wo =(const float*)d_in[5];
        w1 =(const float*)d_in[6];  w2 =(const float*)d_in[7];
        w3 =(const float*)d_in[8];
        maw=(const float*)d_in[9];  mab=(const float*)d_in[10];
        mfw=(const float*)d_in[11]; mfb=(const float*)d_in[12];
        n1 =(const float*)d_in[13]; n2 =(const float*)d_in[14];
        fc =(const float*)d_in[15]; fs =(const float*)d_in[16];
    }
    float* out = (float*)d_out;

    float *p_sv,*p_ma,*p_mf,*p_xn,*p_qkv,*p_attn,*p_h,*p_hn,*p_g1,*p_g3;
    cudaGetSymbolAddress((void**)&p_sv,  g_silu_vec);
    cudaGetSymbolAddress((void**)&p_ma,  g_mod_a);
    cudaGetSymbolAddress((void**)&p_mf,  g_mod_f);
    cudaGetSymbolAddress((void**)&p_xn,  g_xn);
    cudaGetSymbolAddress((void**)&p_qkv, g_qkv);
    cudaGetSymbolAddress((void**)&p_attn,g_attn);
    cudaGetSymbolAddress((void**)&p_h,   g_h);
    cudaGetSymbolAddress((void**)&p_hn,  g_hn);
    cudaGetSymbolAddress((void**)&p_g1,  g_g1);
    cudaGetSymbolAddress((void**)&p_g3,  g_g3);

    cudaFuncSetAttribute(attn_kernel,
                         cudaFuncAttributeMaxDynamicSharedMemorySize, ATT_SMEM);
    cudaFuncSetAttribute(gemm_nt<0>,
                         cudaFuncAttributeMaxDynamicSharedMemorySize, GSMEM);
    cudaFuncSetAttribute(gemm_nt<1>,
                         cudaFuncAttributeMaxDynamicSharedMemorySize, GSMEM);
    cudaFuncSetAttribute(gemm_nt<2>,
                         cudaFuncAttributeMaxDynamicSharedMemorySize, GSMEM);

    /* 1. silu(vec) */
    silu_kernel<<<512, 256>>>(vec, p_sv);

    /* 2. modulation GEMMs (M=512, N=3072, K=1024) + bias */
    gemm_nt<1><<<dim3(24,4), 256, GSMEM>>>(p_sv,DIMN, maw,DIMN, p_ma,3*DIMN, DIMN,
                                           mab, nullptr,0, nullptr,0);
    gemm_nt<1><<<dim3(24,4), 256, GSMEM>>>(p_sv,DIMN, mfw,DIMN, p_mf,3*DIMN, DIMN,
                                           mfb, nullptr,0, nullptr,0);

    /* 3. xn = rmsnorm(x)*(1+scale)+shift */
    rmsnorm_mod_kernel<<<NTOK, 256>>>(x, n1, p_ma, p_xn);

    /* 4. QKV GEMMs into fused (4096 x 1536) buffer */
    gemm_nt<0><<<dim3(8,32), 256, GSMEM>>>(p_xn,DIMN, wq,DIMN, p_qkv,      QKV_LD, DIMN,
                                           nullptr, nullptr,0, nullptr,0);
    gemm_nt<0><<<dim3(2,32), 256, GSMEM>>>(p_xn,DIMN, wk,DIMN, p_qkv+1024, QKV_LD, DIMN,
                                           nullptr, nullptr,0, nullptr,0);
    gemm_nt<0><<<dim3(2,32), 256, GSMEM>>>(p_xn,DIMN, wv,DIMN, p_qkv+1280, QKV_LD, DIMN,
                                           nullptr, nullptr,0, nullptr,0);

    /* 5. RoPE on q + k */
    rope_kernel<<<10240, 256>>>(p_qkv, fc, fs);

    /* 6. block-causal attention */
    attn_kernel<<<dim3(16,16,BATCHN), 256, ATT_SMEM>>>(p_qkv, p_attn);

    /* 7. h = x + gate_a * (attn @ wo^T) */
    gemm_nt<2><<<dim3(8,32), 256, GSMEM>>>(p_attn,DIMN, wo,DIMN, p_h,DIMN, DIMN,
                                           nullptr, x,DIMN, p_ma, 2*DIMN);

    /* 8. hn = rmsnorm(h)*(1+scale_f)+shift_f */
    rmsnorm_mod_kernel<<<NTOK, 256>>>(p_h, n2, p_mf, p_hn);

    /* 9. FFN up projections */
    gemm_nt<0><<<dim3(8,32), 256, GSMEM>>>(p_hn,DIMN, w1,DIMN, p_g1,DIMN, DIMN,
                                           nullptr, nullptr,0, nullptr,0);
    gemm_nt<0><<<dim3(8,32), 256, GSMEM>>>(p_hn,DIMN, w3,DIMN, p_g3,DIMN, DIMN,
                                           nullptr, nullptr,0, nullptr,0);

    /* 10. g1 = silu(g1) * g3 */
    swiglu_kernel<<<4096, 256>>>(p_g1, p_g3);

    /* 11. out = h + gate_f * (g1 @ w2^T) */
    gemm_nt<2><<<dim3(8,32), 256, GSMEM>>>(p_g1,DIMN, w2,DIMN, out,DIMN, DIMN,
                                           nullptr, p_h,DIMN, p_mf, 2*DIMN);
}

// round 8
// speedup vs baseline: 1.5337x; 1.0165x over previous
#include <cuda_runtime.h>
#include <cuda_bf16.h>
#include <math.h>
#include <stdint.h>

#define DIMN   1024
#define SEQL   1024
#define BATCHN 4
#define NTOK   (BATCHN*SEQL)     /* 4096 */
#define NBLK   (BATCHN*128)      /* 512 tokens of vec */
#define QKV_LD 1536
#define EPSV   1e-6f

/* ---------------- scratch (device globals: no allocation allowed) -------- */
__device__ float g_silu_vec[NBLK*DIMN];
__device__ float g_mod_a[NBLK*3*DIMN];
__device__ float g_mod_f[NBLK*3*DIMN];
__device__ float g_xn[NTOK*DIMN];
__device__ float g_qkv[NTOK*QKV_LD];
__device__ float g_attn[NTOK*DIMN];
__device__ float g_h[NTOK*DIMN];
__device__ float g_hn[NTOK*DIMN];
__device__ float g_g1[NTOK*DIMN];
__device__ float g_g3[NTOK*DIMN];

/* hi = truncate-to-bf16 (exact split: x = hi + lo, lo exactly bf16) */
__device__ __forceinline__ uint32_t pack_hi(float x, float y) {
    return __byte_perm(__float_as_uint(x), __float_as_uint(y), 0x7632);
}
__device__ __forceinline__ float hi_part(float x) {
    return __uint_as_float(__float_as_uint(x) & 0xFFFF0000u);
}
/* swizzled word index inside a 128-row x 16-word (32 bf16) tile */
__device__ __forceinline__ int sww(int row, int w) {
    return row*16 + (w ^ (((row >> 1) & 3) << 2));
}
__device__ __forceinline__ void mma_bf16(float* c, const uint32_t* a,
                                         const uint32_t* b) {
    asm volatile(
        "mma.sync.aligned.m16n8k16.row.col.f32.bf16.bf16.f32 "
        "{%0,%1,%2,%3}, {%4,%5,%6,%7}, {%8,%9}, {%0,%1,%2,%3};"
        : "+f"(c[0]), "+f"(c[1]), "+f"(c[2]), "+f"(c[3])
        : "r"(a[0]), "r"(a[1]), "r"(a[2]), "r"(a[3]), "r"(b[0]), "r"(b[1]));
}

/* ------------- split-bf16 GEMM: C(M,N) = A(M,K) @ B(N,K)^T ---------------- */
/* CTA 128x128x32; 8 warps 4x2; warp 32x64 = 2x8 m16n8k16, 3 mma per tile.   */
/* smem: 2 stages x { Ah, Al, Bh, Bl : 128x16 words each } = 65536 B.        */
#define GSMEM 65536

/* MODE 0: single B/C. MODE 1: qkv (3 Bs, C col-offset). MODE 2: dual B/C.   */
/* EPI 0: C=acc; EPI 1: C=acc+bias[n]; EPI 2: C=resid + mod[...]*acc.        */
template<int EPI, int MODE>
__global__ __launch_bounds__(256) void gemm_bf(
    const float* __restrict__ A, int lda,
    const float* __restrict__ B0, const float* __restrict__ B1,
    const float* __restrict__ B2, int ldb,
    float* __restrict__ C0, float* __restrict__ C1, int ldc,
    int K, int split,
    const float* __restrict__ bias0, const float* __restrict__ bias1,
    const float* __restrict__ resid, int ldr,
    const float* __restrict__ mod, int goff) {
    extern __shared__ uint32_t sw[];   /* stage s base = s*8192 words */
    int tid = threadIdx.x, lane = tid & 31, wid = tid >> 5;
    int wm = wid >> 1, wn = wid & 1;
    int g4 = lane >> 2, t4 = lane & 3;
    int bx = blockIdx.x, m0 = blockIdx.y*128;

    const float* Bg; float* Cg; const float* bias = nullptr; int n0loc, n0glob = bx*128;
    if (MODE == 0) {
        Bg = B0 + (size_t)n0glob*ldb; Cg = C0 + n0glob; bias = bias0; n0loc = n0glob;
    } else if (MODE == 1) {
        if (n0glob < 1024)      Bg = B0 + (size_t)n0glob*ldb;
        else if (n0glob < 1280) Bg = B1 + (size_t)(n0glob-1024)*ldb;
        else                    Bg = B2 + (size_t)(n0glob-1280)*ldb;
        Cg = C0 + n0glob; n0loc = n0glob;
    } else {
        int sel = bx >= split; int nb = bx - (sel ? split : 0);
        n0loc = nb*128;
        Bg = (sel ? B1 : B0) + (size_t)n0loc*ldb;
        Cg = (sel ? C1 : C0) + n0loc;
        bias = sel ? bias1 : bias0;
    }
    const float* Ag = A + (size_t)m0 * lda;

    /* ---- stage store helper (inlined twice) ---- */
    /* preload stage 0 */
    {
        uint32_t* Ah = sw;        uint32_t* Al = sw + 2048;
        uint32_t* Bh = sw + 4096; uint32_t* Bl = sw + 6144;
        #pragma unroll
        for (int i = 0; i < 4; i++) {
            int e4 = tid + i*256, r = e4 >> 3, g = e4 & 7;
            float4 va = *(const float4*)(Ag + (size_t)r*lda + g*4);
            float4 vb = *(const float4*)(Bg + (size_t)r*ldb + g*4);
            int idx = sww(r, 2*g);
            float hx, hy, hz, hw;
            hx=hi_part(va.x); hy=hi_part(va.y); hz=hi_part(va.z); hw=hi_part(va.w);
            *(uint2*)&Ah[idx] = make_uint2(pack_hi(va.x,va.y), pack_hi(va.z,va.w));
            *(uint2*)&Al[idx] = make_uint2(pack_hi(va.x-hx,va.y-hy),
                                           pack_hi(va.z-hz,va.w-hw));
            hx=hi_part(vb.x); hy=hi_part(vb.y); hz=hi_part(vb.z); hw=hi_part(vb.w);
            *(uint2*)&Bh[idx] = make_uint2(pack_hi(vb.x,vb.y), pack_hi(vb.z,vb.w));
            *(uint2*)&Bl[idx] = make_uint2(pack_hi(vb.x-hx,vb.y-hy),
                                           pack_hi(vb.z-hz,vb.w-hw));
        }
    }
    __syncthreads();

    float acc[2][8][4];
    #pragma unroll
    for (int mt=0;mt<2;mt++)
        #pragma unroll
        for (int nt=0;nt<8;nt++)
            #pragma unroll
            for (int e=0;e<4;e++) acc[mt][nt][e]=0.f;

    int nk = K >> 5;
    float4 ra[4], rb[4];
    for (int s = 0; s < nk; s++) {
        int cur = s & 1;
        if (s + 1 < nk) {
            int k0 = (s+1)*32;
            #pragma unroll
            for (int i = 0; i < 4; i++) {
                int e4 = tid + i*256, r = e4 >> 3, g = e4 & 7;
                ra[i] = *(const float4*)(Ag + (size_t)r*lda + k0 + g*4);
                rb[i] = *(const float4*)(Bg + (size_t)r*ldb + k0 + g*4);
            }
        }
        const uint32_t* Ah = sw + cur*8192;
        const uint32_t* Al = Ah + 2048;
        const uint32_t* Bh = Ah + 4096;
        const uint32_t* Bl = Ah + 6144;
        #pragma unroll
        for (int half = 0; half < 2; half++) {
            int wq4 = half*8;
            uint32_t ah[2][4], al[2][4], bh[8][2], bl[8][2];
            #pragma unroll
            for (int mt = 0; mt < 2; mt++) {
                int r1 = wm*32 + mt*16 + g4, r2 = r1 + 8, wa = wq4 + t4;
                ah[mt][0]=Ah[sww(r1,wa)];   ah[mt][1]=Ah[sww(r2,wa)];
                ah[mt][2]=Ah[sww(r1,wa+4)]; ah[mt][3]=Ah[sww(r2,wa+4)];
                al[mt][0]=Al[sww(r1,wa)];   al[mt][1]=Al[sww(r2,wa)];
                al[mt][2]=Al[sww(r1,wa+4)]; al[mt][3]=Al[sww(r2,wa+4)];
            }
            #pragma unroll
            for (int nt = 0; nt < 8; nt++) {
                int n = wn*64 + nt*8 + g4, wa = wq4 + t4;
                bh[nt][0]=Bh[sww(n,wa)]; bh[nt][1]=Bh[sww(n,wa+4)];
                bl[nt][0]=Bl[sww(n,wa)]; bl[nt][1]=Bl[sww(n,wa+4)];
            }
            #pragma unroll
            for (int mt = 0; mt < 2; mt++)
                #pragma unroll
                for (int nt = 0; nt < 8; nt++) {
                    mma_bf16(acc[mt][nt], ah[mt], bh[nt]);
                    mma_bf16(acc[mt][nt], ah[mt], bl[nt]);
                    mma_bf16(acc[mt][nt], al[mt], bh[nt]);
                }
        }
        if (s + 1 < nk) {
            uint32_t* Ah2 = sw + (cur^1)*8192;
            uint32_t* Al2 = Ah2 + 2048;
            uint32_t* Bh2 = Ah2 + 4096;
            uint32_t* Bl2 = Ah2 + 6144;
            #pragma unroll
            for (int i = 0; i < 4; i++) {
                int e4 = tid + i*256, r = e4 >> 3, g = e4 & 7;
                int idx = sww(r, 2*g);
                float hx, hy, hz, hw;
                hx=hi_part(ra[i].x); hy=hi_part(ra[i].y);
                hz=hi_part(ra[i].z); hw=hi_part(ra[i].w);
                *(uint2*)&Ah2[idx] = make_uint2(pack_hi(ra[i].x,ra[i].y),
                                                pack_hi(ra[i].z,ra[i].w));
                *(uint2*)&Al2[idx] = make_uint2(pack_hi(ra[i].x-hx,ra[i].y-hy),
                                                pack_hi(ra[i].z-hz,ra[i].w-hw));
                hx=hi_part(rb[i].x); hy=hi_part(rb[i].y);
                hz=hi_part(rb[i].z); hw=hi_part(rb[i].w);
                *(uint2*)&Bh2[idx] = make_uint2(pack_hi(rb[i].x,rb[i].y),
                                                pack_hi(rb[i].z,rb[i].w));
                *(uint2*)&Bl2[idx] = make_uint2(pack_hi(rb[i].x-hx,rb[i].y-hy),
                                                pack_hi(rb[i].z-hz,rb[i].w-hw));
            }
        }
        __syncthreads();
    }

    /* epilogue straight from fragments */
    #pragma unroll
    for (int mt = 0; mt < 2; mt++) {
        int rb0 = m0 + wm*32 + mt*16 + g4;
        #pragma unroll
        for (int h = 0; h < 2; h++) {
            int m = rb0 + h*8;
            #pragma unroll
            for (int nt = 0; nt < 8; nt++) {
                int nl = wn*64 + nt*8 + 2*t4;
                float2 a2 = make_float2(acc[mt][nt][2*h], acc[mt][nt][2*h+1]);
                float2 o;
                if (EPI == 0) {
                    o = a2;
                } else if (EPI == 1) {
                    const float2 bv = *(const float2*)(bias + n0loc + nl);
                    o.x = a2.x + bv.x; o.y = a2.y + bv.y;
                } else {
                    int ng = n0loc + nl;
                    const float2 gv = *(const float2*)(mod + (size_t)(m>>3)*(3*DIMN) + goff + ng);
                    const float2 rv = *(const float2*)(resid + (size_t)m*ldr + ng);
                    o.x = rv.x + gv.x*a2.x;
                    o.y = rv.y + gv.y*a2.y;
                }
                *(float2*)(Cg + (size_t)m*ldc + nl) = o;
            }
        }
    }
}

/* ---------------- elementwise kernels ------------------------------------ */
__global__ __launch_bounds__(256) void silu_kernel(const float* __restrict__ in,
                                                   float* __restrict__ out) {
    int i = blockIdx.x * 256 + threadIdx.x;
    float4 v = ((const float4*)in)[i];
    float4 o;
    o.x = v.x / (1.f + __expf(-v.x));
    o.y = v.y / (1.f + __expf(-v.y));
    o.z = v.z / (1.f + __expf(-v.z));
    o.w = v.w / (1.f + __expf(-v.w));
    ((float4*)out)[i] = o;
}

__global__ __launch_bounds__(256) void swiglu_kernel(float* __restrict__ g1,
                                                     const float* __restrict__ g3) {
    int i = blockIdx.x * 256 + threadIdx.x;
    float4 a = ((float4*)g1)[i];
    float4 b = ((const float4*)g3)[i];
    float4 o;
    o.x = (a.x / (1.f + __expf(-a.x))) * b.x;
    o.y = (a.y / (1.f + __expf(-a.y))) * b.y;
    o.z = (a.z / (1.f + __expf(-a.z))) * b.z;
    o.w = (a.w / (1.f + __expf(-a.w))) * b.w;
    ((float4*)g1)[i] = o;
}

__global__ __launch_bounds__(256) void rmsnorm_mod_kernel(
    const float* __restrict__ X, const float* __restrict__ w,
    const float* __restrict__ mod, float* __restrict__ out) {
    int m = blockIdx.x;
    int tid = threadIdx.x;
    float4 v = ((const float4*)(X + (size_t)m*DIMN))[tid];
    float ss = v.x*v.x + v.y*v.y + v.z*v.z + v.w*v.w;
    #pragma unroll
    for (int o = 16; o; o >>= 1) ss += __shfl_xor_sync(0xffffffffu, ss, o);
    __shared__ float red[8];
    if ((tid & 31) == 0) red[tid >> 5] = ss;
    __syncthreads();
    float tot = red[0]+red[1]+red[2]+red[3]+red[4]+red[5]+red[6]+red[7];
    float rms = rsqrtf(tot * (1.f/DIMN) + EPSV);
    const float* mrow = mod + (size_t)(m >> 3) * (3*DIMN);
    float4 sh = *(const float4*)(mrow + tid*4);
    float4 sc = *(const float4*)(mrow + DIMN + tid*4);
    float4 wv = ((const float4*)w)[tid];
    float4 o;
    o.x = v.x*rms*wv.x*(1.f+sc.x) + sh.x;
    o.y = v.y*rms*wv.y*(1.f+sc.y) + sh.y;
    o.z = v.z*rms*wv.z*(1.f+sc.z) + sh.z;
    o.w = v.w*rms*wv.w*(1.f+sc.w) + sh.w;
    ((float4*)(out + (size_t)m*DIMN))[tid] = o;
}

__global__ __launch_bounds__(256) void rope_kernel(float* __restrict__ qkv,
                                                   const float* __restrict__ cosb,
                                                   const float* __restrict__ sinb) {
    int id = blockIdx.x * 256 + threadIdx.x;
    int d  = id & 31;  id >>= 5;
    int hh = id % 20;  int tg = id / 20;
    int col = (hh < 16) ? hh*64 : 1024 + (hh-16)*64;
    float* p = qkv + (size_t)tg*QKV_LD + col + 2*d;
    int t = tg & (SEQL-1);
    float c = cosb[t*32 + d], s = sinb[t*32 + d];
    float x1 = p[0], x2 = p[1];
    p[0] = x1*c - x2*s;
    p[1] = x1*s + x2*c;
}

/* ---------------- block-causal flash attention ---------------------------- */
#define TPAD 68
#define ATT_SMEM (4*64*TPAD*4 + 2*64*4)

__global__ __launch_bounds__(256) void attn_kernel(const float* __restrict__ qkv,
                                                   float* __restrict__ outp) {
    extern __shared__ float sm[];
    float* Qs = sm;
    float* Ks = Qs + 64*TPAD;
    float* Vt = Ks + 64*TPAD;
    float* Ps = Vt + 64*TPAD;
    float* s_alpha = Ps + 64*TPAD;
    float* s_linv  = s_alpha + 64;

    int qt = blockIdx.x, h = blockIdx.y, b = blockIdx.z;
    int tid = threadIdx.x;
    int rg = tid >> 4, cg = tid & 15;

    const float* qbase = qkv + (size_t)b*SEQL*QKV_LD + h*64;
    const float* kbase = qkv + (size_t)b*SEQL*QKV_LD + 1024 + (h>>2)*64;
    const float* vbase = kbase + 256;

    {   int r = tid >> 2, q4 = tid & 3;
        #pragma unroll
        for (int ii = 0; ii < 4; ii++) {
            int c = (q4 + ii*4)*4;
            *(float4*)&Qs[r*TPAD + c] =
                *(const float4*)(qbase + (size_t)(qt*64 + r)*QKV_LD + c);
        }
    }
    float o[4][4];
    #pragma unroll
    for (int i=0;i<4;i++)
        #pragma unroll
        for (int j=0;j<4;j++) o[i][j]=0.f;
    float mrow = -1e30f, lrow = 0.f;

    for (int kt = 0; kt <= qt; kt++) {
        __syncthreads();
        {   int r = tid >> 2, q4 = tid & 3;
            #pragma unroll
            for (int ii = 0; ii < 4; ii++) {
                int c = (q4 + ii*4)*4;
                *(float4*)&Ks[r*TPAD + c] =
                    *(const float4*)(kbase + (size_t)(kt*64 + r)*QKV_LD + c);
                float4 vv = *(const float4*)(vbase + (size_t)(kt*64 + r)*QKV_LD + c);
                Vt[(c+0)*TPAD + r] = vv.x;
                Vt[(c+1)*TPAD + r] = vv.y;
                Vt[(c+2)*TPAD + r] = vv.z;
                Vt[(c+3)*TPAD + r] = vv.w;
            }
        }
        __syncthreads();

        float acc[4][4];
        #pragma unroll
        for (int i=0;i<4;i++)
            #pragma unroll
            for (int j=0;j<4;j++) acc[i][j]=0.f;
        #pragma unroll
        for (int d0 = 0; d0 < 64; d0 += 4) {
            float4 qa[4], kb[4];
            #pragma unroll
            for (int i=0;i<4;i++) qa[i] = *(const float4*)&Qs[(rg*4+i)*TPAD + d0];
            #pragma unroll
            for (int j=0;j<4;j++) kb[j] = *(const float4*)&Ks[(cg*4+j)*TPAD + d0];
            #pragma unroll
            for (int i=0;i<4;i++)
                #pragma unroll
                for (int j=0;j<4;j++)
                    acc[i][j] += qa[i].x*kb[j].x + qa[i].y*kb[j].y
                               + qa[i].z*kb[j].z + qa[i].w*kb[j].w;
        }
        bool diag = (kt == qt);
        #pragma unroll
        for (int i=0;i<4;i++) {
            int r = rg*4 + i;
            #pragma unroll
            for (int j=0;j<4;j++) {
                int c = cg*4 + j;
                float s = acc[i][j]*0.125f;
                if (diag && ((c>>3) > (r>>3))) s = -1e30f;
                Ps[r*TPAD + c] = s;
            }
        }
        __syncthreads();

        if (tid < 64) {
            float* row = &Ps[tid*TPAD];
            float mx = mrow;
            #pragma unroll 8
            for (int c=0;c<64;c++) mx = fmaxf(mx, row[c]);
            float al = __expf(mrow - mx);
            float sum = 0.f;
            #pragma unroll 8
            for (int c=0;c<64;c++) { float p = __expf(row[c]-mx); row[c]=p; sum+=p; }
            mrow = mx;
            lrow = lrow*al + sum;
            s_alpha[tid] = al;
        }
        __syncthreads();

        float av[4];
        #pragma unroll
        for (int i=0;i<4;i++) av[i] = s_alpha[rg*4+i];
        #pragma unroll
        for (int i=0;i<4;i++)
            #pragma unroll
            for (int j=0;j<4;j++) o[i][j] *= av[i];
        #pragma unroll
        for (int k0 = 0; k0 < 64; k0 += 4) {
            float4 pa[4], vb[4];
            #pragma unroll
            for (int i=0;i<4;i++) pa[i] = *(const float4*)&Ps[(rg*4+i)*TPAD + k0];
            #pragma unroll
            for (int j=0;j<4;j++) vb[j] = *(const float4*)&Vt[(cg*4+j)*TPAD + k0];
            #pragma unroll
            for (int i=0;i<4;i++)
                #pragma unroll
                for (int j=0;j<4;j++)
                    o[i][j] += pa[i].x*vb[j].x + pa[i].y*vb[j].y
                             + pa[i].z*vb[j].z + pa[i].w*vb[j].w;
        }
    }
    __syncthreads();
    if (tid < 64) s_linv[tid] = 1.f / lrow;
    __syncthreads();
    #pragma unroll
    for (int i=0;i<4;i++) {
        float li = s_linv[rg*4+i];
        size_t ro = ((size_t)b*SEQL + qt*64 + rg*4 + i)*DIMN + h*64 + cg*4;
        float4 ov;
        ov.x = o[i][0]*li; ov.y = o[i][1]*li; ov.z = o[i][2]*li; ov.w = o[i][3]*li;
        *(float4*)&outp[ro] = ov;
    }
}

/* ---------------- host launcher ------------------------------------------ */
extern "C" void kernel_launch(void* const* d_in, const int* in_sizes, int n_in,
                              void* d_out, int out_size) {
    const float *x,*vec,*wq,*wk,*wv,*wo,*w1,*w2,*w3,*maw,*mab,*mfw,*mfb,*n1,*n2,*fc,*fs;
    if (in_sizes[2] == 32768) {                   /* reference-argument order */
        x  =(const float*)d_in[0];  vec=(const float*)d_in[1];
        fc =(const float*)d_in[2];  fs =(const float*)d_in[3];
        wq =(const float*)d_in[4];  wk =(const float*)d_in[5];
        wv =(const float*)d_in[6];  wo =(const float*)d_in[7];
        w1 =(const float*)d_in[8];  w2 =(const float*)d_in[9];
        w3 =(const float*)d_in[10];
        maw=(const float*)d_in[11]; mab=(const float*)d_in[12];
        mfw=(const float*)d_in[13]; mfb=(const float*)d_in[14];
        n1 =(const float*)d_in[15]; n2 =(const float*)d_in[16];
    } else {                                      /* setup_inputs dict order */
        x  =(const float*)d_in[0];  vec=(const float*)d_in[1];
        wq =(const float*)d_in[2];  wk =(const float*)d_in[3];
        wv =(const float*)d_in[4];  wo =(const float*)d_in[5];
        w1 =(const float*)d_in[6];  w2 =(const float*)d_in[7];
        w3 =(const float*)d_in[8];
        maw=(const float*)d_in[9];  mab=(const float*)d_in[10];
        mfw=(const float*)d_in[11]; mfb=(const float*)d_in[12];
        n1 =(const float*)d_in[13]; n2 =(const float*)d_in[14];
        fc =(const float*)d_in[15]; fs =(const float*)d_in[16];
    }
    float* out = (float*)d_out;

    float *p_sv,*p_ma,*p_mf,*p_xn,*p_qkv,*p_attn,*p_h,*p_hn,*p_g1,*p_g3;
    cudaGetSymbolAddress((void**)&p_sv,  g_silu_vec);
    cudaGetSymbolAddress((void**)&p_ma,  g_mod_a);
    cudaGetSymbolAddress((void**)&p_mf,  g_mod_f);
    cudaGetSymbolAddress((void**)&p_xn,  g_xn);
    cudaGetSymbolAddress((void**)&p_qkv, g_qkv);
    cudaGetSymbolAddress((void**)&p_attn,g_attn);
    cudaGetSymbolAddress((void**)&p_h,   g_h);
    cudaGetSymbolAddress((void**)&p_hn,  g_hn);
    cudaGetSymbolAddress((void**)&p_g1,  g_g1);
    cudaGetSymbolAddress((void**)&p_g3,  g_g3);

    cudaFuncSetAttribute(attn_kernel,
                         cudaFuncAttributeMaxDynamicSharedMemorySize, ATT_SMEM);
    cudaFuncSetAttribute(gemm_bf<1,2>,
                         cudaFuncAttributeMaxDynamicSharedMemorySize, GSMEM);
    cudaFuncSetAttribute(gemm_bf<0,1>,
                         cudaFuncAttributeMaxDynamicSharedMemorySize, GSMEM);
    cudaFuncSetAttribute(gemm_bf<0,2>,
                         cudaFuncAttributeMaxDynamicSharedMemorySize, GSMEM);
    cudaFuncSetAttribute(gemm_bf<2,0>,
                         cudaFuncAttributeMaxDynamicSharedMemorySize, GSMEM);

    /* 1. silu(vec) */
    silu_kernel<<<512, 256>>>(vec, p_sv);

    /* 2. both modulation GEMMs in one launch (M=512, N=2x3072, K=1024) */
    gemm_bf<1,2><<<dim3(48,4), 256, GSMEM>>>(
        p_sv,DIMN, maw,mfw,nullptr,DIMN, p_ma,p_mf,3*DIMN, DIMN, 24,
        mab,mfb, nullptr,0, nullptr,0);

    /* 3. xn = rmsnorm(x)*(1+scale)+shift */
    rmsnorm_mod_kernel<<<NTOK, 256>>>(x, n1, p_ma, p_xn);

    /* 4. QKV in one launch -> fused (4096 x 1536) buffer */
    gemm_bf<0,1><<<dim3(12,32), 256, GSMEM>>>(
        p_xn,DIMN, wq,wk,wv,DIMN, p_qkv,nullptr,QKV_LD, DIMN, 0,
        nullptr,nullptr, nullptr,0, nullptr,0);

    /* 5. RoPE on q + k */
    rope_kernel<<<10240, 256>>>(p_qkv, fc, fs);

    /* 6. block-causal attention */
    attn_kernel<<<dim3(16,16,BATCHN), 256, ATT_SMEM>>>(p_qkv, p_attn);

    /* 7. h = x + gate_a * (attn @ wo^T) */
    gemm_bf<2,0><<<dim3(8,32), 256, GSMEM>>>(
        p_attn,DIMN, wo,nullptr,nullptr,DIMN, p_h,nullptr,DIMN, DIMN, 0,
        nullptr,nullptr, x,DIMN, p_ma, 2*DIMN);

    /* 8. hn = rmsnorm(h)*(1+scale_f)+shift_f */
    rmsnorm_mod_kernel<<<NTOK, 256>>>(p_h, n2, p_mf, p_hn);

    /* 9. FFN up projections w1 + w3 in one launch */
    gemm_bf<0,2><<<dim3(16,32), 256, GSMEM>>>(
        p_hn,DIMN, w1,w3,nullptr,DIMN, p_g1,p_g3,DIMN, DIMN, 8,
        nullptr,nullptr, nullptr,0, nullptr,0);

    /* 10. g1 = silu(g1) * g3 */
    swiglu_kernel<<<4096, 256>>>(p_g1, p_g3);

    /* 11. out = h + gate_f * (g1 @ w2^T) */
    gemm_bf<2,0><<<dim3(8,32), 256, GSMEM>>>(
        p_g1,DIMN, w2,nullptr,nullptr,DIMN, out,nullptr,DIMN, DIMN, 0,
        nullptr,nullptr, p_h,DIMN, p_mf, 2*DIMN);
}

// round 9
// speedup vs baseline: 1.6932x; 1.1040x over previous
#include <cuda_runtime.h>
#include <cuda_bf16.h>
#include <math.h>
#include <stdint.h>

#define DIMN   1024
#define SEQL   1024
#define BATCHN 4
#define NTOK   (BATCHN*SEQL)     /* 4096 */
#define NBLK   (BATCHN*128)      /* 512 tokens of vec */
#define QKV_LD 1536
#define EPSV   1e-6f

typedef __nv_bfloat16 bf16;

/* ---------------- scratch (device globals: no allocation allowed) -------- */
__device__ float g_mod_a[NBLK*3*DIMN];
__device__ float g_mod_f[NBLK*3*DIMN];
__device__ float g_qkv[NTOK*QKV_LD];
__device__ float g_h[NTOK*DIMN];
__device__ float g_g1[NTOK*DIMN];
__device__ float g_g3[NTOK*DIMN];
/* bf16 hi/lo activation buffers */
__device__ bf16 g_svh[NBLK*DIMN],  g_svl[NBLK*DIMN];
__device__ bf16 g_xnh[NTOK*DIMN],  g_xnl[NTOK*DIMN];
__device__ bf16 g_hnh[NTOK*DIMN],  g_hnl[NTOK*DIMN];
__device__ bf16 g_ath[NTOK*DIMN],  g_atl[NTOK*DIMN];
__device__ bf16 g_g1h[NTOK*DIMN],  g_g1l[NTOK*DIMN];
/* weight hi/lo pool */
#define OWQ  0
#define OWK  1048576
#define OWV  1310720
#define OWO  1572864
#define OW1  2621440
#define OW3  3670016
#define OW2  4718592
#define OMA  5767168
#define OMF  8912896
#define WPOOL 12058624
__device__ bf16 g_wh[WPOOL], g_wl[WPOOL];

/* ---------------- helpers ------------------------------------------------ */
__device__ __forceinline__ uint32_t pack_hi(float x, float y) {
    return __byte_perm(__float_as_uint(x), __float_as_uint(y), 0x7632);
}
__device__ __forceinline__ float hi_part(float x) {
    return __uint_as_float(__float_as_uint(x) & 0xFFFF0000u);
}
__device__ __forceinline__ uint32_t smem_u32(const void* p) {
    uint32_t a;
    asm("{ .reg .u64 t; cvta.to.shared.u64 t, %1; cvt.u32.u64 %0, t; }"
        : "=r"(a) : "l"(p));
    return a;
}
/* word index in a 128-row x 16-word bf16 tile, conflict-free XOR swizzle */
__device__ __forceinline__ int sww16(int r, int w) {
    return r*16 + (w ^ (((r >> 1) & 3) << 2));
}
__device__ __forceinline__ void mma_bf16(float* c, const uint32_t* a,
                                         const uint32_t* b) {
    asm volatile(
        "mma.sync.aligned.m16n8k16.row.col.f32.bf16.bf16.f32 "
        "{%0,%1,%2,%3}, {%4,%5,%6,%7}, {%8,%9}, {%0,%1,%2,%3};"
        : "+f"(c[0]), "+f"(c[1]), "+f"(c[2]), "+f"(c[3])
        : "r"(a[0]), "r"(a[1]), "r"(a[2]), "r"(a[3]), "r"(b[0]), "r"(b[1]));
}

/* ------------- split-bf16 GEMM via cp.async: C = A @ B^T ------------------ */
/* CTA 128x128, BK=32; 3-stage cp.async pipeline; 8 warps 4x2, warp 32x64.   */
/* smem: 3 stages x {Ah,Al,Bh,Bl : 128x16 words} = 98304 B.                  */
#define GSMEM 98304

#define GISSUE(s_) do {                                                        \
    int kof = (s_)*32;                                                         \
    _Pragma("unroll")                                                          \
    for (int i = 0; i < 8; i++) {                                              \
        int id = tid + i*256;                                                  \
        int part = id >> 9, loc = id & 511;                                    \
        int row = loc >> 2, ch = loc & 3;                                      \
        const bf16* sp = (part==0) ? srcAh : (part==1) ? srcAl                 \
                       : (part==2) ? srcBh : srcBl;                            \
        const bf16* src = sp + (size_t)row*K + kof + ch*8;                     \
        uint32_t dst = sb + (uint32_t)((((s_)%3)*8192 + part*2048              \
                       + sww16(row, ch*4)) * 4);                               \
        asm volatile("cp.async.cg.shared.global [%0], [%1], 16;"               \
                     :: "r"(dst), "l"(src) : "memory");                        \
    }                                                                          \
} while (0)

/* MODE 0: single B/C. MODE 1: qkv (3 Bs). MODE 2: dual B/C split by bx.     */
/* EPI 0: C=acc; EPI 1: C=acc+bias[n]; EPI 2: C=resid + mod[...]*acc.        */
template<int EPI, int MODE>
__global__ __launch_bounds__(256, 2) void gemm_bf(
    const bf16* __restrict__ Ah, const bf16* __restrict__ Al,
    const bf16* __restrict__ Bh0, const bf16* __restrict__ Bl0,
    const bf16* __restrict__ Bh1, const bf16* __restrict__ Bl1,
    const bf16* __restrict__ Bh2, const bf16* __restrict__ Bl2,
    float* __restrict__ C0, float* __restrict__ C1, int ldc,
    int K, int split,
    const float* __restrict__ bias0, const float* __restrict__ bias1,
    const float* __restrict__ resid, int ldr,
    const float* __restrict__ mod, int goff) {
    extern __shared__ uint32_t swm[];
    int tid = threadIdx.x, lane = tid & 31, wid = tid >> 5;
    int wm = wid >> 1, wn = wid & 1;
    int g4 = lane >> 2, t4 = lane & 3;
    int bx = blockIdx.x, m0 = blockIdx.y*128;
    int n0glob = bx*128;

    const bf16 *Bh, *Bl; float* Cg; const float* bias = nullptr;
    int n0loc, row0;
    if (MODE == 0) {
        Bh = Bh0; Bl = Bl0; row0 = n0glob; Cg = C0 + n0glob;
        bias = bias0; n0loc = n0glob;
    } else if (MODE == 1) {
        if (n0glob < 1024)      { Bh = Bh0; Bl = Bl0; row0 = n0glob; }
        else if (n0glob < 1280) { Bh = Bh1; Bl = Bl1; row0 = n0glob-1024; }
        else                    { Bh = Bh2; Bl = Bl2; row0 = n0glob-1280; }
        Cg = C0 + n0glob; n0loc = n0glob;
    } else {
        int sel = bx >= split; int nb = bx - (sel ? split : 0);
        n0loc = nb*128; row0 = n0loc;
        Bh = sel ? Bh1 : Bh0;  Bl = sel ? Bl1 : Bl0;
        Cg = (sel ? C1 : C0) + n0loc;
        bias = sel ? bias1 : bias0;
    }
    const bf16* srcAh = Ah + (size_t)m0*K;
    const bf16* srcAl = Al + (size_t)m0*K;
    const bf16* srcBh = Bh + (size_t)row0*K;
    const bf16* srcBl = Bl + (size_t)row0*K;
    uint32_t sb = smem_u32(swm);

    int nk = K >> 5;   /* 32 stages for K=1024 */
    GISSUE(0);
    asm volatile("cp.async.commit_group;" ::: "memory");
    GISSUE(1);
    asm volatile("cp.async.commit_group;" ::: "memory");

    float acc[2][8][4];
    #pragma unroll
    for (int mt=0;mt<2;mt++)
        #pragma unroll
        for (int nt=0;nt<8;nt++)
            #pragma unroll
            for (int e=0;e<4;e++) acc[mt][nt][e]=0.f;

    for (int s = 0; s < nk; s++) {
        asm volatile("cp.async.wait_group 1;" ::: "memory");
        __syncthreads();
        const uint32_t* st  = swm + (s%3)*8192;
        const uint32_t* Als = st + 2048;
        const uint32_t* Bhs = st + 4096;
        const uint32_t* Bls = st + 6144;
        #pragma unroll
        for (int half = 0; half < 2; half++) {
            int wa = half*8 + t4;
            uint32_t ah[2][4], al[2][4];
            #pragma unroll
            for (int mt = 0; mt < 2; mt++) {
                int r1 = wm*32 + mt*16 + g4, r2 = r1 + 8;
                ah[mt][0]=st[sww16(r1,wa)];    ah[mt][1]=st[sww16(r2,wa)];
                ah[mt][2]=st[sww16(r1,wa+4)];  ah[mt][3]=st[sww16(r2,wa+4)];
                al[mt][0]=Als[sww16(r1,wa)];   al[mt][1]=Als[sww16(r2,wa)];
                al[mt][2]=Als[sww16(r1,wa+4)]; al[mt][3]=Als[sww16(r2,wa+4)];
            }
            #pragma unroll
            for (int nt = 0; nt < 8; nt++) {
                int n = wn*64 + nt*8 + g4;
                uint32_t bh[2], bl[2];
                bh[0]=Bhs[sww16(n,wa)]; bh[1]=Bhs[sww16(n,wa+4)];
                bl[0]=Bls[sww16(n,wa)]; bl[1]=Bls[sww16(n,wa+4)];
                #pragma unroll
                for (int mt = 0; mt < 2; mt++) {
                    mma_bf16(acc[mt][nt], ah[mt], bh);
                    mma_bf16(acc[mt][nt], ah[mt], bl);
                    mma_bf16(acc[mt][nt], al[mt], bh);
                }
            }
        }
        if (s + 2 < nk) { GISSUE(s+2); }
        asm volatile("cp.async.commit_group;" ::: "memory");
    }

    /* epilogue straight from fragments */
    #pragma unroll
    for (int mt = 0; mt < 2; mt++) {
        int rb0 = m0 + wm*32 + mt*16 + g4;
        #pragma unroll
        for (int h = 0; h < 2; h++) {
            int m = rb0 + h*8;
            #pragma unroll
            for (int nt = 0; nt < 8; nt++) {
                int nl = wn*64 + nt*8 + 2*t4;
                float2 a2 = make_float2(acc[mt][nt][2*h], acc[mt][nt][2*h+1]);
                float2 o;
                if (EPI == 0) {
                    o = a2;
                } else if (EPI == 1) {
                    const float2 bv = *(const float2*)(bias + n0loc + nl);
                    o.x = a2.x + bv.x; o.y = a2.y + bv.y;
                } else {
                    int ng = n0loc + nl;
                    const float2 gv = *(const float2*)(mod + (size_t)(m>>3)*(3*DIMN) + goff + ng);
                    const float2 rv = *(const float2*)(resid + (size_t)m*ldr + ng);
                    o.x = rv.x + gv.x*a2.x;
                    o.y = rv.y + gv.y*a2.y;
                }
                *(float2*)(Cg + (size_t)m*ldc + nl) = o;
            }
        }
    }
}

/* ---------------- elementwise / convert kernels --------------------------- */
__global__ __launch_bounds__(256) void convert_kernel(
    const float* __restrict__ src, bf16* __restrict__ hi, bf16* __restrict__ lo) {
    int i = blockIdx.x * 256 + threadIdx.x;
    float4 v = ((const float4*)src)[i];
    ((uint2*)hi)[i] = make_uint2(pack_hi(v.x,v.y), pack_hi(v.z,v.w));
    float lx=v.x-hi_part(v.x), ly=v.y-hi_part(v.y);
    float lz=v.z-hi_part(v.z), lw=v.w-hi_part(v.w);
    ((uint2*)lo)[i] = make_uint2(pack_hi(lx,ly), pack_hi(lz,lw));
}

__global__ __launch_bounds__(256) void silu_kernel(
    const float* __restrict__ in, bf16* __restrict__ hi, bf16* __restrict__ lo) {
    int i = blockIdx.x * 256 + threadIdx.x;
    float4 v = ((const float4*)in)[i];
    float4 o;
    o.x = v.x / (1.f + __expf(-v.x));
    o.y = v.y / (1.f + __expf(-v.y));
    o.z = v.z / (1.f + __expf(-v.z));
    o.w = v.w / (1.f + __expf(-v.w));
    ((uint2*)hi)[i] = make_uint2(pack_hi(o.x,o.y), pack_hi(o.z,o.w));
    float lx=o.x-hi_part(o.x), ly=o.y-hi_part(o.y);
    float lz=o.z-hi_part(o.z), lw=o.w-hi_part(o.w);
    ((uint2*)lo)[i] = make_uint2(pack_hi(lx,ly), pack_hi(lz,lw));
}

__global__ __launch_bounds__(256) void swiglu_kernel(
    const float* __restrict__ g1, const float* __restrict__ g3,
    bf16* __restrict__ hi, bf16* __restrict__ lo) {
    int i = blockIdx.x * 256 + threadIdx.x;
    float4 a = ((const float4*)g1)[i];
    float4 b = ((const float4*)g3)[i];
    float4 o;
    o.x = (a.x / (1.f + __expf(-a.x))) * b.x;
    o.y = (a.y / (1.f + __expf(-a.y))) * b.y;
    o.z = (a.z / (1.f + __expf(-a.z))) * b.z;
    o.w = (a.w / (1.f + __expf(-a.w))) * b.w;
    ((uint2*)hi)[i] = make_uint2(pack_hi(o.x,o.y), pack_hi(o.z,o.w));
    float lx=o.x-hi_part(o.x), ly=o.y-hi_part(o.y);
    float lz=o.z-hi_part(o.z), lw=o.w-hi_part(o.w);
    ((uint2*)lo)[i] = make_uint2(pack_hi(lx,ly), pack_hi(lz,lw));
}

/* rmsnorm + adaLN modulate -> bf16 hi/lo outputs */
__global__ __launch_bounds__(256) void rmsnorm_mod_kernel(
    const float* __restrict__ X, const float* __restrict__ w,
    const float* __restrict__ mod, bf16* __restrict__ oh, bf16* __restrict__ ol) {
    int m = blockIdx.x;
    int tid = threadIdx.x;
    float4 v = ((const float4*)(X + (size_t)m*DIMN))[tid];
    float ss = v.x*v.x + v.y*v.y + v.z*v.z + v.w*v.w;
    #pragma unroll
    for (int o = 16; o; o >>= 1) ss += __shfl_xor_sync(0xffffffffu, ss, o);
    __shared__ float red[8];
    if ((tid & 31) == 0) red[tid >> 5] = ss;
    __syncthreads();
    float tot = red[0]+red[1]+red[2]+red[3]+red[4]+red[5]+red[6]+red[7];
    float rms = rsqrtf(tot * (1.f/DIMN) + EPSV);
    const float* mrow = mod + (size_t)(m >> 3) * (3*DIMN);
    float4 sh = *(const float4*)(mrow + tid*4);
    float4 sc = *(const float4*)(mrow + DIMN + tid*4);
    float4 wv = ((const float4*)w)[tid];
    float4 o;
    o.x = v.x*rms*wv.x*(1.f+sc.x) + sh.x;
    o.y = v.y*rms*wv.y*(1.f+sc.y) + sh.y;
    o.z = v.z*rms*wv.z*(1.f+sc.z) + sh.z;
    o.w = v.w*rms*wv.w*(1.f+sc.w) + sh.w;
    ((uint2*)(oh + (size_t)m*DIMN))[tid] = make_uint2(pack_hi(o.x,o.y), pack_hi(o.z,o.w));
    float lx=o.x-hi_part(o.x), ly=o.y-hi_part(o.y);
    float lz=o.z-hi_part(o.z), lw=o.w-hi_part(o.w);
    ((uint2*)(ol + (size_t)m*DIMN))[tid] = make_uint2(pack_hi(lx,ly), pack_hi(lz,lw));
}

__global__ __launch_bounds__(256) void rope_kernel(float* __restrict__ qkv,
                                                   const float* __restrict__ cosb,
                                                   const float* __restrict__ sinb) {
    int id = blockIdx.x * 256 + threadIdx.x;
    int d  = id & 31;  id >>= 5;
    int hh = id % 20;  int tg = id / 20;
    int col = (hh < 16) ? hh*64 : 1024 + (hh-16)*64;
    float* p = qkv + (size_t)tg*QKV_LD + col + 2*d;
    int t = tg & (SEQL-1);
    float c = cosb[t*32 + d], s = sinb[t*32 + d];
    float x1 = p[0], x2 = p[1];
    p[0] = x1*c - x2*s;
    p[1] = x1*s + x2*c;
}

/* ---------------- block-causal flash attention ---------------------------- */
#define TPAD 68
#define ATT_SMEM (4*64*TPAD*4 + 2*64*4)

__global__ __launch_bounds__(256) void attn_kernel(const float* __restrict__ qkv,
                                                   bf16* __restrict__ outh,
                                                   bf16* __restrict__ outl) {
    extern __shared__ float sm[];
    float* Qs = sm;
    float* Ks = Qs + 64*TPAD;
    float* Vt = Ks + 64*TPAD;
    float* Ps = Vt + 64*TPAD;
    float* s_alpha = Ps + 64*TPAD;
    float* s_linv  = s_alpha + 64;

    int qt = blockIdx.x, h = blockIdx.y, b = blockIdx.z;
    int tid = threadIdx.x;
    int rg = tid >> 4, cg = tid & 15;
    int sr = tid >> 2, sj = tid & 3;        /* softmax: 4 threads per row */

    const float* qbase = qkv + (size_t)b*SEQL*QKV_LD + h*64;
    const float* kbase = qkv + (size_t)b*SEQL*QKV_LD + 1024 + (h>>2)*64;
    const float* vbase = kbase + 256;

    {   int r = tid >> 2, q4 = tid & 3;
        #pragma unroll
        for (int ii = 0; ii < 4; ii++) {
            int c = (q4 + ii*4)*4;
            *(float4*)&Qs[r*TPAD + c] =
                *(const float4*)(qbase + (size_t)(qt*64 + r)*QKV_LD + c);
        }
    }
    float o[4][4];
    #pragma unroll
    for (int i=0;i<4;i++)
        #pragma unroll
        for (int j=0;j<4;j++) o[i][j]=0.f;
    float mrow = -1e30f, lrow = 0.f;

    for (int kt = 0; kt <= qt; kt++) {
        __syncthreads();
        {   int r = tid >> 2, q4 = tid & 3;
            #pragma unroll
            for (int ii = 0; ii < 4; ii++) {
                int c = (q4 + ii*4)*4;
                *(float4*)&Ks[r*TPAD + c] =
                    *(const float4*)(kbase + (size_t)(kt*64 + r)*QKV_LD + c);
                float4 vv = *(const float4*)(vbase + (size_t)(kt*64 + r)*QKV_LD + c);
                Vt[(c+0)*TPAD + r] = vv.x;
                Vt[(c+1)*TPAD + r] = vv.y;
                Vt[(c+2)*TPAD + r] = vv.z;
                Vt[(c+3)*TPAD + r] = vv.w;
            }
        }
        __syncthreads();

        float acc[4][4];
        #pragma unroll
        for (int i=0;i<4;i++)
            #pragma unroll
            for (int j=0;j<4;j++) acc[i][j]=0.f;
        #pragma unroll
        for (int d0 = 0; d0 < 64; d0 += 4) {
            float4 qa[4], kb[4];
            #pragma unroll
            for (int i=0;i<4;i++) qa[i] = *(const float4*)&Qs[(rg*4+i)*TPAD + d0];
            #pragma unroll
            for (int j=0;j<4;j++) kb[j] = *(const float4*)&Ks[(cg*4+j)*TPAD + d0];
            #pragma unroll
            for (int i=0;i<4;i++)
                #pragma unroll
                for (int j=0;j<4;j++)
                    acc[i][j] += qa[i].x*kb[j].x + qa[i].y*kb[j].y
                               + qa[i].z*kb[j].z + qa[i].w*kb[j].w;
        }
        bool diag = (kt == qt);
        #pragma unroll
        for (int i=0;i<4;i++) {
            int r = rg*4 + i;
            #pragma unroll
            for (int j=0;j<4;j++) {
                int c = cg*4 + j;
                float s = acc[i][j]*0.125f;
                if (diag && ((c>>3) > (r>>3))) s = -1e30f;
                Ps[r*TPAD + c] = s;
            }
        }
        __syncthreads();

        /* softmax: 4 threads per row, 16 cols each, quad shfl reduce */
        {
            float* row = &Ps[sr*TPAD + sj*16];
            float mx = -1e30f;
            #pragma unroll
            for (int c=0;c<16;c++) mx = fmaxf(mx, row[c]);
            mx = fmaxf(mx, __shfl_xor_sync(0xffffffffu, mx, 1));
            mx = fmaxf(mx, __shfl_xor_sync(0xffffffffu, mx, 2));
            mx = fmaxf(mx, mrow);
            float al = __expf(mrow - mx);
            float sum = 0.f;
            #pragma unroll
            for (int c=0;c<16;c++) { float p = __expf(row[c]-mx); row[c]=p; sum+=p; }
            sum += __shfl_xor_sync(0xffffffffu, sum, 1);
            sum += __shfl_xor_sync(0xffffffffu, sum, 2);
            mrow = mx;
            lrow = lrow*al + sum;
            if (sj == 0) s_alpha[sr] = al;
        }
        __syncthreads();

        float av[4];
        #pragma unroll
        for (int i=0;i<4;i++) av[i] = s_alpha[rg*4+i];
        #pragma unroll
        for (int i=0;i<4;i++)
            #pragma unroll
            for (int j=0;j<4;j++) o[i][j] *= av[i];
        #pragma unroll
        for (int k0 = 0; k0 < 64; k0 += 4) {
            float4 pa[4], vb[4];
            #pragma unroll
            for (int i=0;i<4;i++) pa[i] = *(const float4*)&Ps[(rg*4+i)*TPAD + k0];
            #pragma unroll
            for (int j=0;j<4;j++) vb[j] = *(const float4*)&Vt[(cg*4+j)*TPAD + k0];
            #pragma unroll
            for (int i=0;i<4;i++)
                #pragma unroll
                for (int j=0;j<4;j++)
                    o[i][j] += pa[i].x*vb[j].x + pa[i].y*vb[j].y
                             + pa[i].z*vb[j].z + pa[i].w*vb[j].w;
        }
    }
    __syncthreads();
    if (sj == 0) s_linv[sr & 63] = 1.f / lrow;
    __syncthreads();
    #pragma unroll
    for (int i=0;i<4;i++) {
        float li = s_linv[rg*4+i];
        size_t ro = ((size_t)b*SEQL + qt*64 + rg*4 + i)*DIMN + h*64 + cg*4;
        float vx = o[i][0]*li, vy = o[i][1]*li, vz = o[i][2]*li, vw = o[i][3]*li;
        *(uint2*)&outh[ro] = make_uint2(pack_hi(vx,vy), pack_hi(vz,vw));
        float lx=vx-hi_part(vx), ly=vy-hi_part(vy);
        float lz=vz-hi_part(vz), lw=vw-hi_part(vw);
        *(uint2*)&outl[ro] = make_uint2(pack_hi(lx,ly), pack_hi(lz,lw));
    }
}

/* ---------------- host launcher ------------------------------------------ */
extern "C" void kernel_launch(void* const* d_in, const int* in_sizes, int n_in,
                              void* d_out, int out_size) {
    const float *x,*vec,*wq,*wk,*wv,*wo,*w1,*w2,*w3,*maw,*mab,*mfw,*mfb,*n1,*n2,*fc,*fs;
    if (in_sizes[2] == 32768) {                   /* reference-argument order */
        x  =(const float*)d_in[0];  vec=(const float*)d_in[1];
        fc =(const float*)d_in[2];  fs =(const float*)d_in[3];
        wq =(const float*)d_in[4];  wk =(const float*)d_in[5];
        wv =(const float*)d_in[6];  wo =(const float*)d_in[7];
        w1 =(const float*)d_in[8];  w2 =(const float*)d_in[9];
        w3 =(const float*)d_in[10];
        maw=(const float*)d_in[11]; mab=(const float*)d_in[12];
        mfw=(const float*)d_in[13]; mfb=(const float*)d_in[14];
        n1 =(const float*)d_in[15]; n2 =(const float*)d_in[16];
    } else {                                      /* setup_inputs dict order */
        x  =(const float*)d_in[0];  vec=(const float*)d_in[1];
        wq =(const float*)d_in[2];  wk =(const float*)d_in[3];
        wv =(const float*)d_in[4];  wo =(const float*)d_in[5];
        w1 =(const float*)d_in[6];  w2 =(const float*)d_in[7];
        w3 =(const float*)d_in[8];
        maw=(const float*)d_in[9];  mab=(const float*)d_in[10];
        mfw=(const float*)d_in[11]; mfb=(const float*)d_in[12];
        n1 =(const float*)d_in[13]; n2 =(const float*)d_in[14];
        fc =(const float*)d_in[15]; fs =(const float*)d_in[16];
    }
    float* out = (float*)d_out;

    float *p_ma,*p_mf,*p_qkv,*p_h,*p_g1,*p_g3;
    bf16 *p_svh,*p_svl,*p_xnh,*p_xnl,*p_hnh,*p_hnl,*p_ath,*p_atl,*p_g1h,*p_g1l,*p_wh,*p_wl;
    cudaGetSymbolAddress((void**)&p_ma,  g_mod_a);
    cudaGetSymbolAddress((void**)&p_mf,  g_mod_f);
    cudaGetSymbolAddress((void**)&p_qkv, g_qkv);
    cudaGetSymbolAddress((void**)&p_h,   g_h);
    cudaGetSymbolAddress((void**)&p_g1,  g_g1);
    cudaGetSymbolAddress((void**)&p_g3,  g_g3);
    cudaGetSymbolAddress((void**)&p_svh, g_svh);
    cudaGetSymbolAddress((void**)&p_svl, g_svl);
    cudaGetSymbolAddress((void**)&p_xnh, g_xnh);
    cudaGetSymbolAddress((void**)&p_xnl, g_xnl);
    cudaGetSymbolAddress((void**)&p_hnh, g_hnh);
    cudaGetSymbolAddress((void**)&p_hnl, g_hnl);
    cudaGetSymbolAddress((void**)&p_ath, g_ath);
    cudaGetSymbolAddress((void**)&p_atl, g_atl);
    cudaGetSymbolAddress((void**)&p_g1h, g_g1h);
    cudaGetSymbolAddress((void**)&p_g1l, g_g1l);
    cudaGetSymbolAddress((void**)&p_wh,  g_wh);
    cudaGetSymbolAddress((void**)&p_wl,  g_wl);

    cudaFuncSetAttribute(attn_kernel,
                         cudaFuncAttributeMaxDynamicSharedMemorySize, ATT_SMEM);
    cudaFuncSetAttribute(gemm_bf<1,2>,
                         cudaFuncAttributeMaxDynamicSharedMemorySize, GSMEM);
    cudaFuncSetAttribute(gemm_bf<0,1>,
                         cudaFuncAttributeMaxDynamicSharedMemorySize, GSMEM);
    cudaFuncSetAttribute(gemm_bf<0,2>,
                         cudaFuncAttributeMaxDynamicSharedMemorySize, GSMEM);
    cudaFuncSetAttribute(gemm_bf<2,0>,
                         cudaFuncAttributeMaxDynamicSharedMemorySize, GSMEM);

    /* 0. convert all weights to bf16 hi/lo (once per launch) */
    convert_kernel<<<1024, 256>>>(wq,  p_wh+OWQ, p_wl+OWQ);
    convert_kernel<<<256,  256>>>(wk,  p_wh+OWK, p_wl+OWK);
    convert_kernel<<<256,  256>>>(wv,  p_wh+OWV, p_wl+OWV);
    convert_kernel<<<1024, 256>>>(wo,  p_wh+OWO, p_wl+OWO);
    convert_kernel<<<1024, 256>>>(w1,  p_wh+OW1, p_wl+OW1);
    convert_kernel<<<1024, 256>>>(w3,  p_wh+OW3, p_wl+OW3);
    convert_kernel<<<1024, 256>>>(w2,  p_wh+OW2, p_wl+OW2);
    convert_kernel<<<3072, 256>>>(maw, p_wh+OMA, p_wl+OMA);
    convert_kernel<<<3072, 256>>>(mfw, p_wh+OMF, p_wl+OMF);

    /* 1. silu(vec) -> hi/lo */
    silu_kernel<<<512, 256>>>(vec, p_svh, p_svl);

    /* 2. both modulation GEMMs in one launch */
    gemm_bf<1,2><<<dim3(48,4), 256, GSMEM>>>(
        p_svh,p_svl, p_wh+OMA,p_wl+OMA, p_wh+OMF,p_wl+OMF, nullptr,nullptr,
        p_ma,p_mf,3*DIMN, DIMN, 24, mab,mfb, nullptr,0, nullptr,0);

    /* 3. xn = rmsnorm(x)*(1+scale)+shift -> hi/lo */
    rmsnorm_mod_kernel<<<NTOK, 256>>>(x, n1, p_ma, p_xnh, p_xnl);

    /* 4. QKV in one launch */
    gemm_bf<0,1><<<dim3(12,32), 256, GSMEM>>>(
        p_xnh,p_xnl, p_wh+OWQ,p_wl+OWQ, p_wh+OWK,p_wl+OWK, p_wh+OWV,p_wl+OWV,
        p_qkv,nullptr,QKV_LD, DIMN, 0, nullptr,nullptr, nullptr,0, nullptr,0);

    /* 5. RoPE on q + k */
    rope_kernel<<<10240, 256>>>(p_qkv, fc, fs);

    /* 6. block-causal attention -> hi/lo */
    attn_kernel<<<dim3(16,16,BATCHN), 256, ATT_SMEM>>>(p_qkv, p_ath, p_atl);

    /* 7. h = x + gate_a * (attn @ wo^T) */
    gemm_bf<2,0><<<dim3(8,32), 256, GSMEM>>>(
        p_ath,p_atl, p_wh+OWO,p_wl+OWO, nullptr,nullptr, nullptr,nullptr,
        p_h,nullptr,DIMN, DIMN, 0, nullptr,nullptr, x,DIMN, p_ma, 2*DIMN);

    /* 8. hn -> hi/lo */
    rmsnorm_mod_kernel<<<NTOK, 256>>>(p_h, n2, p_mf, p_hnh, p_hnl);

    /* 9. FFN up: w1 + w3 in one launch */
    gemm_bf<0,2><<<dim3(16,32), 256, GSMEM>>>(
        p_hnh,p_hnl, p_wh+OW1,p_wl+OW1, p_wh+OW3,p_wl+OW3, nullptr,nullptr,
        p_g1,p_g3,DIMN, DIMN, 8, nullptr,nullptr, nullptr,0, nullptr,0);

    /* 10. swiglu -> hi/lo */
    swiglu_kernel<<<4096, 256>>>(p_g1, p_g3, p_g1h, p_g1l);

    /* 11. out = h + gate_f * (swiglu @ w2^T) */
    gemm_bf<2,0><<<dim3(8,32), 256, GSMEM>>>(
        p_g1h,p_g1l, p_wh+OW2,p_wl+OW2, nullptr,nullptr, nullptr,nullptr,
        out,nullptr,DIMN, DIMN, 0, nullptr,nullptr, p_h,DIMN, p_mf, 2*DIMN);
}

// round 10
// speedup vs baseline: 3.1268x; 1.8467x over previous
#include <cuda_runtime.h>
#include <cuda_bf16.h>
#include <math.h>
#include <stdint.h>

#define DIMN   1024
#define SEQL   1024
#define BATCHN 4
#define NTOK   (BATCHN*SEQL)     /* 4096 */
#define NBLK   (BATCHN*128)      /* 512 tokens of vec */
#define QKV_LD 1536
#define EPSV   1e-6f

typedef __nv_bfloat16 bf16;

/* ---------------- scratch (device globals: no allocation allowed) -------- */
__device__ float g_mod_a[NBLK*3*DIMN];
__device__ float g_mod_f[NBLK*3*DIMN];
__device__ float g_qkv[NTOK*QKV_LD];
__device__ float g_h[NTOK*DIMN];
__device__ float g_g1[NTOK*DIMN];
__device__ float g_g3[NTOK*DIMN];
/* bf16 hi/lo activation buffers */
__device__ bf16 g_svh[NBLK*DIMN],  g_svl[NBLK*DIMN];
__device__ bf16 g_xnh[NTOK*DIMN],  g_xnl[NTOK*DIMN];
__device__ bf16 g_hnh[NTOK*DIMN],  g_hnl[NTOK*DIMN];
__device__ bf16 g_ath[NTOK*DIMN],  g_atl[NTOK*DIMN];
__device__ bf16 g_g1h[NTOK*DIMN],  g_g1l[NTOK*DIMN];
/* rope'd q/k in bf16 hi/lo, row stride 768 words (1536 bf16) */
__device__ uint32_t g_qkh[NTOK*768], g_qkl[NTOK*768];
/* weight hi/lo pool */
#define OWQ  0
#define OWK  1048576
#define OWV  1310720
#define OWO  1572864
#define OW1  2621440
#define OW3  3670016
#define OW2  4718592
#define OMA  5767168
#define OMF  8912896
#define WPOOL 12058624
__device__ bf16 g_wh[WPOOL], g_wl[WPOOL];

/* ---------------- helpers ------------------------------------------------ */
__device__ __forceinline__ uint32_t pack_hi(float x, float y) {
    return __byte_perm(__float_as_uint(x), __float_as_uint(y), 0x7632);
}
__device__ __forceinline__ float hi_part(float x) {
    return __uint_as_float(__float_as_uint(x) & 0xFFFF0000u);
}
__device__ __forceinline__ uint32_t smem_u32(const void* p) {
    uint32_t a;
    asm("{ .reg .u64 t; cvta.to.shared.u64 t, %1; cvt.u32.u64 %0, t; }"
        : "=r"(a) : "l"(p));
    return a;
}
/* word index in a 128-row x 16-word bf16 tile, conflict-free XOR swizzle */
__device__ __forceinline__ int sww16(int r, int w) {
    return r*16 + (w ^ (((r >> 1) & 3) << 2));
}
/* word index, 32-word (64 bf16) rows */
__device__ __forceinline__ int sww32(int r, int w) {
    return r*32 + (w ^ (((r) & 7) << 2));
}
__device__ __forceinline__ void mma_bf16(float* c, const uint32_t* a,
                                         const uint32_t* b) {
    asm volatile(
        "mma.sync.aligned.m16n8k16.row.col.f32.bf16.bf16.f32 "
        "{%0,%1,%2,%3}, {%4,%5,%6,%7}, {%8,%9}, {%0,%1,%2,%3};"
        : "+f"(c[0]), "+f"(c[1]), "+f"(c[2]), "+f"(c[3])
        : "r"(a[0]), "r"(a[1]), "r"(a[2]), "r"(a[3]), "r"(b[0]), "r"(b[1]));
}
/* fast exp on FMA pipe: 2^(x*log2e), deg-5 poly, clamp handles -1e30 mask */
__device__ __forceinline__ float fexp(float x) {
    float t = fmaxf(x * 1.44269504f, -126.f);
    float fi = floorf(t);
    float f = t - fi;
    float p = fmaf(f, 0.00133336f, 0.00961812f);
    p = fmaf(f, p, 0.05550411f);
    p = fmaf(f, p, 0.24022651f);
    p = fmaf(f, p, 0.69314718f);
    p = fmaf(f, p, 1.0f);
    return __int_as_float(((int)fi + 127) << 23) * p;
}

/* ------------- split-bf16 GEMM via cp.async: C = A @ B^T ------------------ */
#define GSMEM 98304

#define GISSUE(s_) do {                                                        \
    int kof = (s_)*32;                                                         \
    _Pragma("unroll")                                                          \
    for (int i = 0; i < 8; i++) {                                              \
        int id = tid + i*256;                                                  \
        int part = id >> 9, loc = id & 511;                                    \
        int row = loc >> 2, ch = loc & 3;                                      \
        const bf16* sp = (part==0) ? srcAh : (part==1) ? srcAl                 \
                       : (part==2) ? srcBh : srcBl;                            \
        const bf16* src = sp + (size_t)row*K + kof + ch*8;                     \
        uint32_t dst = sb + (uint32_t)((((s_)%3)*8192 + part*2048              \
                       + sww16(row, ch*4)) * 4);                               \
        asm volatile("cp.async.cg.shared.global [%0], [%1], 16;"               \
                     :: "r"(dst), "l"(src) : "memory");                        \
    }                                                                          \
} while (0)

template<int EPI, int MODE>
__global__ __launch_bounds__(256, 2) void gemm_bf(
    const bf16* __restrict__ Ah, const bf16* __restrict__ Al,
    const bf16* __restrict__ Bh0, const bf16* __restrict__ Bl0,
    const bf16* __restrict__ Bh1, const bf16* __restrict__ Bl1,
    const bf16* __restrict__ Bh2, const bf16* __restrict__ Bl2,
    float* __restrict__ C0, float* __restrict__ C1, int ldc,
    int K, int split,
    const float* __restrict__ bias0, const float* __restrict__ bias1,
    const float* __restrict__ resid, int ldr,
    const float* __restrict__ mod, int goff) {
    extern __shared__ uint32_t swm[];
    int tid = threadIdx.x, lane = tid & 31, wid = tid >> 5;
    int wm = wid >> 1, wn = wid & 1;
    int g4 = lane >> 2, t4 = lane & 3;
    int bx = blockIdx.x, m0 = blockIdx.y*128;
    int n0glob = bx*128;

    const bf16 *Bh, *Bl; float* Cg; const float* bias = nullptr;
    int n0loc, row0;
    if (MODE == 0) {
        Bh = Bh0; Bl = Bl0; row0 = n0glob; Cg = C0 + n0glob;
        bias = bias0; n0loc = n0glob;
    } else if (MODE == 1) {
        if (n0glob < 1024)      { Bh = Bh0; Bl = Bl0; row0 = n0glob; }
        else if (n0glob < 1280) { Bh = Bh1; Bl = Bl1; row0 = n0glob-1024; }
        else                    { Bh = Bh2; Bl = Bl2; row0 = n0glob-1280; }
        Cg = C0 + n0glob; n0loc = n0glob;
    } else {
        int sel = bx >= split; int nb = bx - (sel ? split : 0);
        n0loc = nb*128; row0 = n0loc;
        Bh = sel ? Bh1 : Bh0;  Bl = sel ? Bl1 : Bl0;
        Cg = (sel ? C1 : C0) + n0loc;
        bias = sel ? bias1 : bias0;
    }
    const bf16* srcAh = Ah + (size_t)m0*K;
    const bf16* srcAl = Al + (size_t)m0*K;
    const bf16* srcBh = Bh + (size_t)row0*K;
    const bf16* srcBl = Bl + (size_t)row0*K;
    uint32_t sb = smem_u32(swm);

    int nk = K >> 5;
    GISSUE(0);
    asm volatile("cp.async.commit_group;" ::: "memory");
    GISSUE(1);
    asm volatile("cp.async.commit_group;" ::: "memory");

    float acc[2][8][4];
    #pragma unroll
    for (int mt=0;mt<2;mt++)
        #pragma unroll
        for (int nt=0;nt<8;nt++)
            #pragma unroll
            for (int e=0;e<4;e++) acc[mt][nt][e]=0.f;

    for (int s = 0; s < nk; s++) {
        asm volatile("cp.async.wait_group 1;" ::: "memory");
        __syncthreads();
        const uint32_t* st  = swm + (s%3)*8192;
        const uint32_t* Als = st + 2048;
        const uint32_t* Bhs = st + 4096;
        const uint32_t* Bls = st + 6144;
        #pragma unroll
        for (int half = 0; half < 2; half++) {
            int wa = half*8 + t4;
            uint32_t ah[2][4], al[2][4];
            #pragma unroll
            for (int mt = 0; mt < 2; mt++) {
                int r1 = wm*32 + mt*16 + g4, r2 = r1 + 8;
                ah[mt][0]=st[sww16(r1,wa)];    ah[mt][1]=st[sww16(r2,wa)];
                ah[mt][2]=st[sww16(r1,wa+4)];  ah[mt][3]=st[sww16(r2,wa+4)];
                al[mt][0]=Als[sww16(r1,wa)];   al[mt][1]=Als[sww16(r2,wa)];
                al[mt][2]=Als[sww16(r1,wa+4)]; al[mt][3]=Als[sww16(r2,wa+4)];
            }
            #pragma unroll
            for (int nt = 0; nt < 8; nt++) {
                int n = wn*64 + nt*8 + g4;
                uint32_t bh[2], bl[2];
                bh[0]=Bhs[sww16(n,wa)]; bh[1]=Bhs[sww16(n,wa+4)];
                bl[0]=Bls[sww16(n,wa)]; bl[1]=Bls[sww16(n,wa+4)];
                #pragma unroll
                for (int mt = 0; mt < 2; mt++) {
                    mma_bf16(acc[mt][nt], ah[mt], bh);
                    mma_bf16(acc[mt][nt], ah[mt], bl);
                    mma_bf16(acc[mt][nt], al[mt], bh);
                }
            }
        }
        if (s + 2 < nk) { GISSUE(s+2); }
        asm volatile("cp.async.commit_group;" ::: "memory");
    }

    #pragma unroll
    for (int mt = 0; mt < 2; mt++) {
        int rb0 = m0 + wm*32 + mt*16 + g4;
        #pragma unroll
        for (int h = 0; h < 2; h++) {
            int m = rb0 + h*8;
            #pragma unroll
            for (int nt = 0; nt < 8; nt++) {
                int nl = wn*64 + nt*8 + 2*t4;
                float2 a2 = make_float2(acc[mt][nt][2*h], acc[mt][nt][2*h+1]);
                float2 o;
                if (EPI == 0) {
                    o = a2;
                } else if (EPI == 1) {
                    const float2 bv = *(const float2*)(bias + n0loc + nl);
                    o.x = a2.x + bv.x; o.y = a2.y + bv.y;
                } else {
                    int ng = n0loc + nl;
                    const float2 gv = *(const float2*)(mod + (size_t)(m>>3)*(3*DIMN) + goff + ng);
                    const float2 rv = *(const float2*)(resid + (size_t)m*ldr + ng);
                    o.x = rv.x + gv.x*a2.x;
                    o.y = rv.y + gv.y*a2.y;
                }
                *(float2*)(Cg + (size_t)m*ldc + nl) = o;
            }
        }
    }
}

/* ---------------- fused weight convert (9 segments, 1 launch) ------------- */
__global__ __launch_bounds__(256) void conv_all(
    const float* __restrict__ wq, const float* __restrict__ wk,
    const float* __restrict__ wv, const float* __restrict__ wo,
    const float* __restrict__ w1, const float* __restrict__ w3,
    const float* __restrict__ w2, const float* __restrict__ maw,
    const float* __restrict__ mfw,
    bf16* __restrict__ wh, bf16* __restrict__ wl) {
    int bb = blockIdx.x;
    const float* src; int loc, dof;
    if      (bb < 1024)  { src = wq;  loc = bb;       dof = OWQ; }
    else if (bb < 1280)  { src = wk;  loc = bb-1024;  dof = OWK; }
    else if (bb < 1536)  { src = wv;  loc = bb-1280;  dof = OWV; }
    else if (bb < 2560)  { src = wo;  loc = bb-1536;  dof = OWO; }
    else if (bb < 3584)  { src = w1;  loc = bb-2560;  dof = OW1; }
    else if (bb < 4608)  { src = w3;  loc = bb-3584;  dof = OW3; }
    else if (bb < 5632)  { src = w2;  loc = bb-4608;  dof = OW2; }
    else if (bb < 8704)  { src = maw; loc = bb-5632;  dof = OMA; }
    else                 { src = mfw; loc = bb-8704;  dof = OMF; }
    int i = loc*256 + threadIdx.x;
    float4 v = ((const float4*)src)[i];
    ((uint2*)(wh + dof))[i] = make_uint2(pack_hi(v.x,v.y), pack_hi(v.z,v.w));
    float lx=v.x-hi_part(v.x), ly=v.y-hi_part(v.y);
    float lz=v.z-hi_part(v.z), lw=v.w-hi_part(v.w);
    ((uint2*)(wl + dof))[i] = make_uint2(pack_hi(lx,ly), pack_hi(lz,lw));
}

/* ---------------- elementwise kernels ------------------------------------ */
__global__ __launch_bounds__(256) void silu_kernel(
    const float* __restrict__ in, bf16* __restrict__ hi, bf16* __restrict__ lo) {
    int i = blockIdx.x * 256 + threadIdx.x;
    float4 v = ((const float4*)in)[i];
    float4 o;
    o.x = v.x / (1.f + __expf(-v.x));
    o.y = v.y / (1.f + __expf(-v.y));
    o.z = v.z / (1.f + __expf(-v.z));
    o.w = v.w / (1.f + __expf(-v.w));
    ((uint2*)hi)[i] = make_uint2(pack_hi(o.x,o.y), pack_hi(o.z,o.w));
    float lx=o.x-hi_part(o.x), ly=o.y-hi_part(o.y);
    float lz=o.z-hi_part(o.z), lw=o.w-hi_part(o.w);
    ((uint2*)lo)[i] = make_uint2(pack_hi(lx,ly), pack_hi(lz,lw));
}

__global__ __launch_bounds__(256) void swiglu_kernel(
    const float* __restrict__ g1, const float* __restrict__ g3,
    bf16* __restrict__ hi, bf16* __restrict__ lo) {
    int i = blockIdx.x * 256 + threadIdx.x;
    float4 a = ((const float4*)g1)[i];
    float4 b = ((const float4*)g3)[i];
    float4 o;
    o.x = (a.x / (1.f + __expf(-a.x))) * b.x;
    o.y = (a.y / (1.f + __expf(-a.y))) * b.y;
    o.z = (a.z / (1.f + __expf(-a.z))) * b.z;
    o.w = (a.w / (1.f + __expf(-a.w))) * b.w;
    ((uint2*)hi)[i] = make_uint2(pack_hi(o.x,o.y), pack_hi(o.z,o.w));
    float lx=o.x-hi_part(o.x), ly=o.y-hi_part(o.y);
    float lz=o.z-hi_part(o.z), lw=o.w-hi_part(o.w);
    ((uint2*)lo)[i] = make_uint2(pack_hi(lx,ly), pack_hi(lz,lw));
}

__global__ __launch_bounds__(256) void rmsnorm_mod_kernel(
    const float* __restrict__ X, const float* __restrict__ w,
    const float* __restrict__ mod, bf16* __restrict__ oh, bf16* __restrict__ ol) {
    int m = blockIdx.x;
    int tid = threadIdx.x;
    float4 v = ((const float4*)(X + (size_t)m*DIMN))[tid];
    float ss = v.x*v.x + v.y*v.y + v.z*v.z + v.w*v.w;
    #pragma unroll
    for (int o = 16; o; o >>= 1) ss += __shfl_xor_sync(0xffffffffu, ss, o);
    __shared__ float red[8];
    if ((tid & 31) == 0) red[tid >> 5] = ss;
    __syncthreads();
    float tot = red[0]+red[1]+red[2]+red[3]+red[4]+red[5]+red[6]+red[7];
    float rms = rsqrtf(tot * (1.f/DIMN) + EPSV);
    const float* mrow = mod + (size_t)(m >> 3) * (3*DIMN);
    float4 sh = *(const float4*)(mrow + tid*4);
    float4 sc = *(const float4*)(mrow + DIMN + tid*4);
    float4 wv = ((const float4*)w)[tid];
    float4 o;
    o.x = v.x*rms*wv.x*(1.f+sc.x) + sh.x;
    o.y = v.y*rms*wv.y*(1.f+sc.y) + sh.y;
    o.z = v.z*rms*wv.z*(1.f+sc.z) + sh.z;
    o.w = v.w*rms*wv.w*(1.f+sc.w) + sh.w;
    ((uint2*)(oh + (size_t)m*DIMN))[tid] = make_uint2(pack_hi(o.x,o.y), pack_hi(o.z,o.w));
    float lx=o.x-hi_part(o.x), ly=o.y-hi_part(o.y);
    float lz=o.z-hi_part(o.z), lw=o.w-hi_part(o.w);
    ((uint2*)(ol + (size_t)m*DIMN))[tid] = make_uint2(pack_hi(lx,ly), pack_hi(lz,lw));
}

/* rope q/k cols [0,1280) of qkv -> bf16 hi/lo buffers (row stride 768 words)*/
__global__ __launch_bounds__(256) void rope_bf_kernel(
    const float* __restrict__ qkv, const float* __restrict__ cosb,
    const float* __restrict__ sinb,
    uint32_t* __restrict__ qh, uint32_t* __restrict__ ql) {
    int i = blockIdx.x*256 + threadIdx.x;     /* 1,310,720 items */
    int c4 = (i % 320)*4;
    int tg = i / 320;
    float4 v = *(const float4*)(qkv + (size_t)tg*QKV_LD + c4);
    int t = tg & (SEQL-1);
    int dp = (c4 & 63) >> 1;
    float c0 = cosb[t*32+dp],   s0 = sinb[t*32+dp];
    float c1 = cosb[t*32+dp+1], s1 = sinb[t*32+dp+1];
    float r0 = v.x*c0 - v.y*s0, r1 = v.x*s0 + v.y*c0;
    float r2 = v.z*c1 - v.w*s1, r3 = v.z*s1 + v.w*c1;
    int w = (tg*QKV_LD + c4) >> 1;
    qh[w]   = pack_hi(r0, r1);
    qh[w+1] = pack_hi(r2, r3);
    ql[w]   = pack_hi(r0-hi_part(r0), r1-hi_part(r1));
    ql[w+1] = pack_hi(r2-hi_part(r2), r3-hi_part(r3));
}

/* ---------------- mma block-causal flash attention ------------------------ */
/* CTA: 128 q-rows (qt2), 1 head, 1 batch. 8 warps x 16 rows.                */
/* smem words: Qh[0,4096) Ql[4096) Kh[8192) Kl[10240) Vh[12288) Vl[14336)    */
#define ATT_SMEM 65536

__global__ __launch_bounds__(256, 2) void attn_kernel(
    const uint32_t* __restrict__ qkh, const uint32_t* __restrict__ qkl,
    const float* __restrict__ qkv,
    bf16* __restrict__ outh, bf16* __restrict__ outl) {
    extern __shared__ uint32_t sm[];
    uint32_t* Qh = sm;
    uint32_t* Ql = sm + 4096;
    uint32_t* Kh = sm + 8192;
    uint32_t* Kl = sm + 10240;
    uint32_t* Vh = sm + 12288;
    uint32_t* Vl = sm + 14336;
    int qt2 = blockIdx.x, h = blockIdx.y, b = blockIdx.z;
    int tid = threadIdx.x, lane = tid & 31, wid = tid >> 5;
    int g4 = lane >> 2, t4 = lane & 3;

    /* load Q (128 rows x 64 cols) hi/lo */
    {
        const uint32_t* qs = qkh + ((size_t)(b*SEQL + qt2*128))*768 + h*32;
        const uint32_t* qsl = qkl + ((size_t)(b*SEQL + qt2*128))*768 + h*32;
        #pragma unroll
        for (int i = 0; i < 8; i++) {
            int id = tid + i*256;
            int r = id >> 4, u = (id & 15)*2;
            *(uint2*)&Qh[sww32(r, u)] = *(const uint2*)(qs + (size_t)r*768 + u);
            *(uint2*)&Ql[sww32(r, u)] = *(const uint2*)(qsl + (size_t)r*768 + u);
        }
    }

    int kmax = 2*qt2 + (wid >> 2);
    int rb01 = (wid & 3)*2, rb23 = rb01 + 1;
    int base_r = wid*16;
    float s[8][4], o[8][4];
    float m0 = -1e30f, m1 = -1e30f, l0 = 0.f, l1 = 0.f;
    #pragma unroll
    for (int nt=0;nt<8;nt++)
        #pragma unroll
        for (int e=0;e<4;e++) o[nt][e]=0.f;

    int ktend = 2*qt2 + 1;
    for (int kt = 0; kt <= ktend; kt++) {
        __syncthreads();
        /* load K tile hi/lo */
        {
            const uint32_t* ks = qkh + ((size_t)(b*SEQL + kt*64))*768 + 512 + (h>>2)*32;
            const uint32_t* ksl = qkl + ((size_t)(b*SEQL + kt*64))*768 + 512 + (h>>2)*32;
            #pragma unroll
            for (int i = 0; i < 4; i++) {
                int id = tid + i*256;
                int r = id >> 4, u = (id & 15)*2;
                *(uint2*)&Kh[sww32(r, u)] = *(const uint2*)(ks + (size_t)r*768 + u);
                *(uint2*)&Kl[sww32(r, u)] = *(const uint2*)(ksl + (size_t)r*768 + u);
            }
        }
        /* load + transpose + split V tile (fp32 source) */
        {
            const float* vs = qkv + ((size_t)(b*SEQL + kt*64))*QKV_LD + 1280 + (h>>2)*64;
            #pragma unroll
            for (int i = 0; i < 2; i++) {
                int it = tid + i*256;
                int tp = it & 31, dg = it >> 5;
                float4 va = *(const float4*)(vs + (size_t)(2*tp)*QKV_LD + dg*4);
                float4 vb = *(const float4*)(vs + (size_t)(2*tp+1)*QKV_LD + dg*4);
                float ax[4] = {va.x, va.y, va.z, va.w};
                float bx[4] = {vb.x, vb.y, vb.z, vb.w};
                #pragma unroll
                for (int dd = 0; dd < 4; dd++) {
                    int d = dg*4 + dd;
                    Vh[sww32(d, tp)] = pack_hi(ax[dd], bx[dd]);
                    Vl[sww32(d, tp)] = pack_hi(ax[dd]-hi_part(ax[dd]),
                                               bx[dd]-hi_part(bx[dd]));
                }
            }
        }
        __syncthreads();
        if (kt > kmax) continue;

        /* S = Q @ K^T (split bf16, 3 mma) */
        #pragma unroll
        for (int nt=0;nt<8;nt++)
            #pragma unroll
            for (int e=0;e<4;e++) s[nt][e]=0.f;
        #pragma unroll
        for (int ks = 0; ks < 4; ks++) {
            int wa = ks*8 + t4;
            int r1 = base_r + g4, r2 = r1 + 8;
            uint32_t ah[4], al[4];
            ah[0]=Qh[sww32(r1,wa)];   ah[1]=Qh[sww32(r2,wa)];
            ah[2]=Qh[sww32(r1,wa+4)]; ah[3]=Qh[sww32(r2,wa+4)];
            al[0]=Ql[sww32(r1,wa)];   al[1]=Ql[sww32(r2,wa)];
            al[2]=Ql[sww32(r1,wa+4)]; al[3]=Ql[sww32(r2,wa+4)];
            #pragma unroll
            for (int nt = 0; nt < 8; nt++) {
                int n = nt*8 + g4;
                uint32_t bh[2], bl[2];
                bh[0]=Kh[sww32(n,wa)]; bh[1]=Kh[sww32(n,wa+4)];
                bl[0]=Kl[sww32(n,wa)]; bl[1]=Kl[sww32(n,wa+4)];
                mma_bf16(s[nt], ah, bh);
                mma_bf16(s[nt], ah, bl);
                mma_bf16(s[nt], al, bh);
            }
        }
        /* scale + causal mask (boundary tile only) */
        #pragma unroll
        for (int nt=0;nt<8;nt++)
            #pragma unroll
            for (int e=0;e<4;e++) s[nt][e] *= 0.125f;
        if (kt == kmax) {
            #pragma unroll
            for (int nt=0;nt<8;nt++) {
                if (nt > rb01) { s[nt][0] = -1e30f; s[nt][1] = -1e30f; }
                if (nt > rb23) { s[nt][2] = -1e30f; s[nt][3] = -1e30f; }
            }
        }
        /* online softmax (rows g4 and g4+8) */
        float mx0 = -1e30f, mx1 = -1e30f;
        #pragma unroll
        for (int nt=0;nt<8;nt++) {
            mx0 = fmaxf(mx0, fmaxf(s[nt][0], s[nt][1]));
            mx1 = fmaxf(mx1, fmaxf(s[nt][2], s[nt][3]));
        }
        mx0 = fmaxf(mx0, __shfl_xor_sync(0xffffffffu, mx0, 1));
        mx0 = fmaxf(mx0, __shfl_xor_sync(0xffffffffu, mx0, 2));
        mx1 = fmaxf(mx1, __shfl_xor_sync(0xffffffffu, mx1, 1));
        mx1 = fmaxf(mx1, __shfl_xor_sync(0xffffffffu, mx1, 2));
        float nm0 = fmaxf(m0, mx0), nm1 = fmaxf(m1, mx1);
        float al0 = fexp(m0 - nm0), al1 = fexp(m1 - nm1);
        m0 = nm0; m1 = nm1;
        float sum0 = 0.f, sum1 = 0.f;
        #pragma unroll
        for (int nt=0;nt<8;nt++) {
            s[nt][0] = fexp(s[nt][0] - m0);
            s[nt][1] = fexp(s[nt][1] - m0);
            s[nt][2] = fexp(s[nt][2] - m1);
            s[nt][3] = fexp(s[nt][3] - m1);
            sum0 += s[nt][0] + s[nt][1];
            sum1 += s[nt][2] + s[nt][3];
        }
        sum0 += __shfl_xor_sync(0xffffffffu, sum0, 1);
        sum0 += __shfl_xor_sync(0xffffffffu, sum0, 2);
        sum1 += __shfl_xor_sync(0xffffffffu, sum1, 1);
        sum1 += __shfl_xor_sync(0xffffffffu, sum1, 2);
        l0 = l0*al0 + sum0;
        l1 = l1*al1 + sum1;
        #pragma unroll
        for (int nt=0;nt<8;nt++) {
            o[nt][0] *= al0; o[nt][1] *= al0;
            o[nt][2] *= al1; o[nt][3] *= al1;
        }
        /* O += P @ V (P fragments from S regs, split bf16) */
        #pragma unroll
        for (int ks = 0; ks < 4; ks++) {
            uint32_t ph[4], pl[4];
            ph[0] = pack_hi(s[2*ks][0],   s[2*ks][1]);
            ph[1] = pack_hi(s[2*ks][2],   s[2*ks][3]);
            ph[2] = pack_hi(s[2*ks+1][0], s[2*ks+1][1]);
            ph[3] = pack_hi(s[2*ks+1][2], s[2*ks+1][3]);
            pl[0] = pack_hi(s[2*ks][0]-hi_part(s[2*ks][0]),
                            s[2*ks][1]-hi_part(s[2*ks][1]));
            pl[1] = pack_hi(s[2*ks][2]-hi_part(s[2*ks][2]),
                            s[2*ks][3]-hi_part(s[2*ks][3]));
            pl[2] = pack_hi(s[2*ks+1][0]-hi_part(s[2*ks+1][0]),
                            s[2*ks+1][1]-hi_part(s[2*ks+1][1]));
            pl[3] = pack_hi(s[2*ks+1][2]-hi_part(s[2*ks+1][2]),
                            s[2*ks+1][3]-hi_part(s[2*ks+1][3]));
            int wa = ks*8 + t4;
            #pragma unroll
            for (int nt = 0; nt < 8; nt++) {
                int n = nt*8 + g4;
                uint32_t bh[2], bl[2];
                bh[0]=Vh[sww32(n,wa)]; bh[1]=Vh[sww32(n,wa+4)];
                bl[0]=Vl[sww32(n,wa)]; bl[1]=Vl[sww32(n,wa+4)];
                mma_bf16(o[nt], ph, bh);
                mma_bf16(o[nt], ph, bl);
                mma_bf16(o[nt], pl, bh);
            }
        }
    }

    /* normalize and write bf16 hi/lo */
    float i0 = 1.f / l0, i1 = 1.f / l1;
    int tok0 = b*SEQL + qt2*128 + base_r + g4;
    #pragma unroll
    for (int nt = 0; nt < 8; nt++) {
        int col = h*64 + nt*8 + 2*t4;
        float x0 = o[nt][0]*i0, x1 = o[nt][1]*i0;
        float x2 = o[nt][2]*i1, x3 = o[nt][3]*i1;
        ((uint32_t*)outh)[((size_t)tok0*DIMN + col) >> 1] = pack_hi(x0, x1);
        ((uint32_t*)outl)[((size_t)tok0*DIMN + col) >> 1] =
            pack_hi(x0-hi_part(x0), x1-hi_part(x1));
        ((uint32_t*)outh)[((size_t)(tok0+8)*DIMN + col) >> 1] = pack_hi(x2, x3);
        ((uint32_t*)outl)[((size_t)(tok0+8)*DIMN + col) >> 1] =
            pack_hi(x2-hi_part(x2), x3-hi_part(x3));
    }
}

/* ---------------- host launcher ------------------------------------------ */
extern "C" void kernel_launch(void* const* d_in, const int* in_sizes, int n_in,
                              void* d_out, int out_size) {
    const float *x,*vec,*wq,*wk,*wv,*wo,*w1,*w2,*w3,*maw,*mab,*mfw,*mfb,*n1,*n2,*fc,*fs;
    if (in_sizes[2] == 32768) {                   /* reference-argument order */
        x  =(const float*)d_in[0];  vec=(const float*)d_in[1];
        fc =(const float*)d_in[2];  fs =(const float*)d_in[3];
        wq =(const float*)d_in[4];  wk =(const float*)d_in[5];
        wv =(const float*)d_in[6];  wo =(const float*)d_in[7];
        w1 =(const float*)d_in[8];  w2 =(const float*)d_in[9];
        w3 =(const float*)d_in[10];
        maw=(const float*)d_in[11]; mab=(const float*)d_in[12];
        mfw=(const float*)d_in[13]; mfb=(const float*)d_in[14];
        n1 =(const float*)d_in[15]; n2 =(const float*)d_in[16];
    } else {                                      /* setup_inputs dict order */
        x  =(const float*)d_in[0];  vec=(const float*)d_in[1];
        wq =(const float*)d_in[2];  wk =(const float*)d_in[3];
        wv =(const float*)d_in[4];  wo =(const float*)d_in[5];
        w1 =(const float*)d_in[6];  w2 =(const float*)d_in[7];
        w3 =(const float*)d_in[8];
        maw=(const float*)d_in[9];  mab=(const float*)d_in[10];
        mfw=(const float*)d_in[11]; mfb=(const float*)d_in[12];
        n1 =(const float*)d_in[13]; n2 =(const float*)d_in[14];
        fc =(const float*)d_in[15]; fs =(const float*)d_in[16];
    }
    float* out = (float*)d_out;

    float *p_ma,*p_mf,*p_qkv,*p_h,*p_g1,*p_g3;
    bf16 *p_svh,*p_svl,*p_xnh,*p_xnl,*p_hnh,*p_hnl,*p_ath,*p_atl,*p_g1h,*p_g1l,*p_wh,*p_wl;
    uint32_t *p_qkh,*p_qkl;
    cudaGetSymbolAddress((void**)&p_ma,  g_mod_a);
    cudaGetSymbolAddress((void**)&p_mf,  g_mod_f);
    cudaGetSymbolAddress((void**)&p_qkv, g_qkv);
    cudaGetSymbolAddress((void**)&p_h,   g_h);
    cudaGetSymbolAddress((void**)&p_g1,  g_g1);
    cudaGetSymbolAddress((void**)&p_g3,  g_g3);
    cudaGetSymbolAddress((void**)&p_svh, g_svh);
    cudaGetSymbolAddress((void**)&p_svl, g_svl);
    cudaGetSymbolAddress((void**)&p_xnh, g_xnh);
    cudaGetSymbolAddress((void**)&p_xnl, g_xnl);
    cudaGetSymbolAddress((void**)&p_hnh, g_hnh);
    cudaGetSymbolAddress((void**)&p_hnl, g_hnl);
    cudaGetSymbolAddress((void**)&p_ath, g_ath);
    cudaGetSymbolAddress((void**)&p_atl, g_atl);
    cudaGetSymbolAddress((void**)&p_g1h, g_g1h);
    cudaGetSymbolAddress((void**)&p_g1l, g_g1l);
    cudaGetSymbolAddress((void**)&p_wh,  g_wh);
    cudaGetSymbolAddress((void**)&p_wl,  g_wl);
    cudaGetSymbolAddress((void**)&p_qkh, g_qkh);
    cudaGetSymbolAddress((void**)&p_qkl, g_qkl);

    cudaFuncSetAttribute(attn_kernel,
                         cudaFuncAttributeMaxDynamicSharedMemorySize, ATT_SMEM);
    cudaFuncSetAttribute(gemm_bf<1,2>,
                         cudaFuncAttributeMaxDynamicSharedMemorySize, GSMEM);
    cudaFuncSetAttribute(gemm_bf<0,1>,
                         cudaFuncAttributeMaxDynamicSharedMemorySize, GSMEM);
    cudaFuncSetAttribute(gemm_bf<0,2>,
                         cudaFuncAttributeMaxDynamicSharedMemorySize, GSMEM);
    cudaFuncSetAttribute(gemm_bf<2,0>,
                         cudaFuncAttributeMaxDynamicSharedMemorySize, GSMEM);

    /* 0. all weight converts in one launch */
    conv_all<<<11776, 256>>>(wq, wk, wv, wo, w1, w3, w2, maw, mfw, p_wh, p_wl);

    /* 1. silu(vec) -> hi/lo */
    silu_kernel<<<512, 256>>>(vec, p_svh, p_svl);

    /* 2. both modulation GEMMs in one launch */
    gemm_bf<1,2><<<dim3(48,4), 256, GSMEM>>>(
        p_svh,p_svl, p_wh+OMA,p_wl+OMA, p_wh+OMF,p_wl+OMF, nullptr,nullptr,
        p_ma,p_mf,3*DIMN, DIMN, 24, mab,mfb, nullptr,0, nullptr,0);

    /* 3. xn -> hi/lo */
    rmsnorm_mod_kernel<<<NTOK, 256>>>(x, n1, p_ma, p_xnh, p_xnl);

    /* 4. QKV in one launch -> fp32 qkv buffer */
    gemm_bf<0,1><<<dim3(12,32), 256, GSMEM>>>(
        p_xnh,p_xnl, p_wh+OWQ,p_wl+OWQ, p_wh+OWK,p_wl+OWK, p_wh+OWV,p_wl+OWV,
        p_qkv,nullptr,QKV_LD, DIMN, 0, nullptr,nullptr, nullptr,0, nullptr,0);

    /* 5. RoPE q/k -> bf16 hi/lo buffers */
    rope_bf_kernel<<<5120, 256>>>(p_qkv, fc, fs, p_qkh, p_qkl);

    /* 6. mma block-causal attention -> hi/lo */
    attn_kernel<<<dim3(8,16,BATCHN), 256, ATT_SMEM>>>(p_qkh, p_qkl, p_qkv,
                                                      p_ath, p_atl);

    /* 7. h = x + gate_a * (attn @ wo^T) */
    gemm_bf<2,0><<<dim3(8,32), 256, GSMEM>>>(
        p_ath,p_atl, p_wh+OWO,p_wl+OWO, nullptr,nullptr, nullptr,nullptr,
        p_h,nullptr,DIMN, DIMN, 0, nullptr,nullptr, x,DIMN, p_ma, 2*DIMN);

    /* 8. hn -> hi/lo */
    rmsnorm_mod_kernel<<<NTOK, 256>>>(p_h, n2, p_mf, p_hnh, p_hnl);

    /* 9. FFN up: w1 + w3 in one launch */
    gemm_bf<0,2><<<dim3(16,32), 256, GSMEM>>>(
        p_hnh,p_hnl, p_wh+OW1,p_wl+OW1, p_wh+OW3,p_wl+OW3, nullptr,nullptr,
        p_g1,p_g3,DIMN, DIMN, 8, nullptr,nullptr, nullptr,0, nullptr,0);

    /* 10. swiglu -> hi/lo */
    swiglu_kernel<<<4096, 256>>>(p_g1, p_g3, p_g1h, p_g1l);

    /* 11. out = h + gate_f * (swiglu @ w2^T) */
    gemm_bf<2,0><<<dim3(8,32), 256, GSMEM>>>(
        p_g1h,p_g1l, p_wh+OW2,p_wl+OW2, nullptr,nullptr, nullptr,nullptr,
        out,nullptr,DIMN, DIMN, 0, nullptr,nullptr, p_h,DIMN, p_mf, 2*DIMN);
}